// round 6
// baseline (speedup 1.0000x reference)
#include <cuda_runtime.h>
#include <cstdint>

#define LPn 4096
#define LHn 4096
#define Dn 300
#define Hn 512
#define NSPLIT 4

// ---------------- scratch (device globals; no allocation allowed) ----------
__device__ float g_emb[(LPn + LHn) * Dn];  // p rows then h rows (tf32-rounded)
__device__ float g_t1[(LPn + LHn) * Hn];
__device__ float g_fa[(LPn + LHn) * Hn];   // attend out: fp | fh (rounded)
__device__ float g_t2[(LPn + LHn) * Hn];
__device__ float g_cat[(LPn + LHn) * 2 * Dn];
__device__ float g_part[NSPLIT * LPn * Dn];
__device__ float g_eik[LPn];
__device__ float g_ekj[LHn];
__device__ float g_v[2 * Hn];
__device__ float g_wa1[Hn * Dn];
__device__ float g_wa2[Hn * Hn];
__device__ float g_wc1[Hn * 2 * Dn];
__device__ float g_wc2[Hn * Hn];
__device__ float g_fhT[LHn * Hn];    // transpose of reshape(fh,[H,LH]) -> [LH, H]
__device__ float g_hembT[Dn * LHn];  // [300, 4096]
__device__ float g_pembT[Dn * LPn];  // [300, 4096]

// ---------------- helpers ---------------------------------------------------
__device__ __forceinline__ uint32_t f2tf(float x) {
    uint32_t u;
    asm("cvt.rna.tf32.f32 %0, %1;" : "=r"(u) : "f"(x));
    return u;
}
__device__ __forceinline__ float roundtf(float x) { return __uint_as_float(f2tf(x)); }

__device__ __forceinline__ void cpa16(uint32_t saddr, const float* g, uint32_t vb) {
    asm volatile("cp.async.cg.shared.global [%0], [%1], 16, %2;"
                 ::"r"(saddr), "l"(g), "r"(vb));
}
#define CP_COMMIT() asm volatile("cp.async.commit_group;" ::: "memory")
#define CP_WAIT1() asm volatile("cp.async.wait_group 1;" ::: "memory")

__device__ __forceinline__ void mma8(float* c, const uint32_t* a, uint32_t b0, uint32_t b1) {
    asm volatile(
        "mma.sync.aligned.m16n8k8.row.col.f32.tf32.tf32.f32 "
        "{%0,%1,%2,%3}, {%4,%5,%6,%7}, {%8,%9}, {%0,%1,%2,%3};"
        : "+f"(c[0]), "+f"(c[1]), "+f"(c[2]), "+f"(c[3])
        : "r"(a[0]), "r"(a[1]), "r"(a[2]), "r"(a[3]), "r"(b0), "r"(b1));
}

__device__ __forceinline__ void ldm4(uint32_t* r, uint32_t addr) {
    asm volatile("ldmatrix.sync.aligned.m8n8.x4.shared.b16 {%0,%1,%2,%3}, [%4];"
                 : "=r"(r[0]), "=r"(r[1]), "=r"(r[2]), "=r"(r[3]) : "r"(addr));
}

// direct: src row-major [rows, ld]; chunk cols [k0,k0+32) -> smem [r][k] stride 36
__device__ __forceinline__ void loadDirectAsync(const float* __restrict__ src, int ld,
                                                int row0, int rlim, int k0, int kend,
                                                uint32_t saddr) {
    int t = threadIdx.x;
    int r = t >> 1, half = (t & 1) * 16;
    int gr = row0 + r;
    bool rok = gr < rlim;
    const float* p = src + (size_t)(rok ? gr : row0) * ld + k0 + half;
    uint32_t sa = saddr + (uint32_t)(r * 36 + half) * 4;
#pragma unroll
    for (int j = 0; j < 4; j++) {
        int gk = k0 + half + j * 4;
        uint32_t vb = (rok && gk + 3 < kend) ? 16u : 0u;
        cpa16(sa + j * 16, p + j * 4, vb);
    }
}

// trans: src row-major [Ktot, ld]; rows [k0,k0+32), cols [c0,c0+128) -> smem [k][c] stride 136
__device__ __forceinline__ void loadTransAsync(const float* __restrict__ src, int ld,
                                               int c0, int clim, int k0, int kend,
                                               uint32_t saddr) {
    int t = threadIdx.x;
    int k = t >> 3;
    int gk = k0 + k;
    bool kok = gk < kend;
    const float* p = src + (size_t)(kok ? gk : k0) * ld + c0;
    uint32_t sa = saddr + (uint32_t)(k * 136) * 4;
#pragma unroll
    for (int j = 0; j < 4; j++) {
        int c = ((t & 7) + j * 8) * 4;
        uint32_t vb = (kok && c0 + c + 3 < clim) ? 16u : 0u;
        cpa16(sa + (uint32_t)c * 4, p + c, vb);
    }
}

// ---------------- mma.sync tf32 GEMM, cp.async 3-stage, ldmatrix -----------
// C[M,N] = A @ B.
//   AT=0: A row-major [M,K] (ldmatrix). AT=1: A[m,k]=src[k*lda+m] (scalar LDS).
//   B is ALWAYS W-form [N,K] row-major -> smem [n][k] stride 36 (ldmatrix).
// EPI: 0 none; 1 bias+relu (aux=bias[N]).  ROUND: tf32-round stores.
// SPLITK: blockIdx.z picks K range, C += z*M*ldc (partials).
template <bool AT, int EPI, bool ROUND, bool SPLITK>
__global__ void __launch_bounds__(256, 2)
tgemm(const float* __restrict__ A, int lda,
      const float* __restrict__ B, int ldb,
      const float* __restrict__ aux,
      float* __restrict__ C, int ldc,
      int M, int N, int K, int Ksub) {
    constexpr int AW = AT ? 32 * 136 : 128 * 36;
    constexpr int BW = 128 * 36;
    constexpr int STW = AW + BW;
    extern __shared__ uint32_t sm[];
    const uint32_t sbase = (uint32_t)__cvta_generic_to_shared(sm);

    const int tid = threadIdx.x, wid = tid >> 5, lane = tid & 31;
    const int gid = lane >> 2, tig = lane & 3;
    const int wm = wid >> 1, wn = wid & 1;
    const int bm = blockIdx.y * 128, bn = blockIdx.x * 128;

    int k_off = 0, Kloc = K;
    if (SPLITK) {
        k_off = blockIdx.z * Ksub;
        Kloc = Ksub;
        C += (size_t)blockIdx.z * M * ldc;
    }
    const int kend = k_off + Kloc;
    const int NC = (Kloc + 31) / 32;

    float acc[2][8][4];
#pragma unroll
    for (int i = 0; i < 2; i++)
#pragma unroll
        for (int j = 0; j < 8; j++)
#pragma unroll
            for (int q = 0; q < 4; q++) acc[i][j][q] = 0.f;

    // per-thread ldmatrix base offsets (within a stage)
    const uint32_t a_lm_off =
        (uint32_t)((wm * 32 + (lane & 15)) * 36 + ((lane >> 4) << 2)) * 4;
    const uint32_t b_lm_off =
        (uint32_t)AW * 4 +
        (uint32_t)((wn * 64 + (lane & 7) + ((lane >> 4) << 3)) * 36 + (((lane >> 3) & 1) << 2)) * 4;

    // prologue: chunks 0,1 -> stages 0,1
#pragma unroll
    for (int pc = 0; pc < 2; pc++) {
        uint32_t sA = sbase + (uint32_t)(pc * STW) * 4;
        uint32_t sB = sA + (uint32_t)AW * 4;
        int k0 = k_off + pc * 32;
        if (AT) loadTransAsync(A, lda, bm, M, k0, kend, sA);
        else    loadDirectAsync(A, lda, bm, M, k0, kend, sA);
        loadDirectAsync(B, ldb, bn, N, k0, kend, sB);
        CP_COMMIT();
    }

    for (int kc = 0; kc < NC; kc++) {
        CP_WAIT1();
        __syncthreads();
        if (kc + 2 < NC) {
            int st = (kc + 2) % 3;
            int k0 = k_off + (kc + 2) * 32;
            uint32_t sA = sbase + (uint32_t)(st * STW) * 4;
            uint32_t sB = sA + (uint32_t)AW * 4;
            if (AT) loadTransAsync(A, lda, bm, M, k0, kend, sA);
            else    loadDirectAsync(A, lda, bm, M, k0, kend, sA);
            loadDirectAsync(B, ldb, bn, N, k0, kend, sB);
        }
        CP_COMMIT();

        const uint32_t stoff = (uint32_t)((kc % 3) * STW) * 4;
        const uint32_t* SA_p = sm + (kc % 3) * STW;
#pragma unroll
        for (int kk = 0; kk < 4; kk++) {
            int k8 = kk * 8;
            uint32_t a[2][4];
            if (AT) {
#pragma unroll
                for (int mi = 0; mi < 2; mi++) {
                    int m0 = wm * 32 + mi * 16;
                    a[mi][0] = SA_p[(k8 + tig) * 136 + m0 + gid];
                    a[mi][1] = SA_p[(k8 + tig) * 136 + m0 + gid + 8];
                    a[mi][2] = SA_p[(k8 + tig + 4) * 136 + m0 + gid];
                    a[mi][3] = SA_p[(k8 + tig + 4) * 136 + m0 + gid + 8];
                }
            } else {
                uint32_t ab = sbase + stoff + a_lm_off + (uint32_t)k8 * 4;
                ldm4(a[0], ab);
                ldm4(a[1], ab + 16 * 36 * 4);
            }
            uint32_t b[8][2];
#pragma unroll
            for (int nj = 0; nj < 4; nj++) {
                uint32_t r[4];
                ldm4(r, sbase + stoff + b_lm_off + (uint32_t)(nj * 16 * 36 + k8) * 4);
                b[2 * nj][0] = r[0]; b[2 * nj][1] = r[1];
                b[2 * nj + 1][0] = r[2]; b[2 * nj + 1][1] = r[3];
            }
#pragma unroll
            for (int ni = 0; ni < 8; ni++) {
                mma8(acc[0][ni], a[0], b[ni][0], b[ni][1]);
                mma8(acc[1][ni], a[1], b[ni][0], b[ni][1]);
            }
        }
    }

    // epilogue
#pragma unroll
    for (int mi = 0; mi < 2; mi++) {
#pragma unroll
        for (int ni = 0; ni < 8; ni++) {
            int col = bn + wn * 64 + ni * 8 + tig * 2;
            if (col >= N) continue;
            int r0 = bm + wm * 32 + mi * 16 + gid;
            float v0 = acc[mi][ni][0], v1 = acc[mi][ni][1];
            float v2 = acc[mi][ni][2], v3 = acc[mi][ni][3];
            if (EPI == 1) {
                float bi0 = aux[col];
                float bi1 = (col + 1 < N) ? aux[col + 1] : 0.f;
                v0 = fmaxf(v0 + bi0, 0.f); v1 = fmaxf(v1 + bi1, 0.f);
                v2 = fmaxf(v2 + bi0, 0.f); v3 = fmaxf(v3 + bi1, 0.f);
            }
            if (ROUND) {
                v0 = roundtf(v0); v1 = roundtf(v1);
                v2 = roundtf(v2); v3 = roundtf(v3);
            }
            float* c0p = C + (size_t)r0 * ldc + col;
            float* c1p = C + (size_t)(r0 + 8) * ldc + col;
            if (col + 1 < N) {
                *(float2*)c0p = make_float2(v0, v1);
                *(float2*)c1p = make_float2(v2, v3);
            } else {
                *c0p = v0;
                *c1p = v2;
            }
        }
    }
}

// ---------------- small kernels -------------------------------------------
__global__ void gather4_k(const int* __restrict__ idx, const float* __restrict__ emb,
                          float* __restrict__ dst, int rows) {
    int t = blockIdx.x * blockDim.x + threadIdx.x;
    if (t < rows * (Dn / 4)) {
        int r = t / (Dn / 4), c = t - r * (Dn / 4);
        float4 v = ((const float4*)(emb + (size_t)idx[r] * Dn))[c];
        v.x = roundtf(v.x); v.y = roundtf(v.y);
        v.z = roundtf(v.z); v.w = roundtf(v.w);
        ((float4*)dst)[t] = v;
    }
}

__global__ void cvtw_k(const float* __restrict__ w, float* __restrict__ dst, int n) {
    int t = blockIdx.x * blockDim.x + threadIdx.x;
    if (t < n) dst[t] = roundtf(w[t]);
}

// dst[c][r] = src[r][c]; src [R, C] row-major
__global__ void transpose_k(const float* __restrict__ src, float* __restrict__ dst,
                            int R, int C) {
    __shared__ float tile[32][33];
    int c = blockIdx.x * 32 + threadIdx.x;
    int r = blockIdx.y * 32 + threadIdx.y;
#pragma unroll
    for (int i = 0; i < 32; i += 8)
        if (r + i < R && c < C) tile[threadIdx.y + i][threadIdx.x] = src[(size_t)(r + i) * C + c];
    __syncthreads();
    int c2 = blockIdx.y * 32 + threadIdx.x;  // = src row
    int r2 = blockIdx.x * 32 + threadIdx.y;  // = src col
#pragma unroll
    for (int i = 0; i < 32; i += 8)
        if (r2 + i < C && c2 < R) dst[(size_t)(r2 + i) * R + c2] = tile[threadIdx.x][threadIdx.y + i];
}

__global__ void zero_k() {
    int t = blockIdx.x * blockDim.x + threadIdx.x;
    if (t < LHn) g_ekj[t] = 0.f;
    if (t < 2 * Hn) g_v[t] = 0.f;
}

__global__ void rowsum_k(const float* __restrict__ E, float* __restrict__ out) {
    int row = blockIdx.x * (blockDim.x / 32) + (threadIdx.x >> 5);
    int lane = threadIdx.x & 31;
    const float4* p = (const float4*)(E + (size_t)row * LHn);
    float s = 0.f;
    for (int j = lane; j < LHn / 4; j += 32) {
        float4 v = p[j];
        s += (v.x + v.y) + (v.z + v.w);
    }
#pragma unroll
    for (int o = 16; o; o >>= 1) s += __shfl_xor_sync(0xffffffffu, s, o);
    if (lane == 0) out[row] = s;
}

__global__ void colsum_acc_k(const float* __restrict__ X, float* __restrict__ out,
                             int cols, int rows_per_blk) {
    int col = blockIdx.x * blockDim.x + threadIdx.x;
    if (col >= cols) return;
    long r0 = (long)blockIdx.y * rows_per_blk;
    float s = 0.f;
    for (long r = r0; r < r0 + rows_per_blk; r++) s += X[r * cols + col];
    atomicAdd(&out[col], s);
}

__global__ void concat_k(const float* __restrict__ beta, const float* __restrict__ alpha,
                         float* __restrict__ dst) {
    int t = blockIdx.x * blockDim.x + threadIdx.x;
    if (t >= (LPn + LHn) * (2 * Dn / 4)) return;
    int R = t / (2 * Dn / 4), c4 = t - R * (2 * Dn / 4);
    float4 v;
    if (c4 < Dn / 4) {
        v = ((const float4*)(g_emb + (size_t)R * Dn))[c4];  // already rounded
    } else {
        const float* src = (R < LPn) ? (beta + (size_t)R * Dn)
                                     : (alpha + (size_t)(R - LPn) * Dn);
        v = ((const float4*)src)[c4 - Dn / 4];
        v.x = roundtf(v.x); v.y = roundtf(v.y);
        v.z = roundtf(v.z); v.w = roundtf(v.w);
    }
    ((float4*)dst)[t] = v;
}

// sum NSPLIT partials, scale rows by 1/scale[row]
__global__ void reduce_scale_k(const float* __restrict__ part,
                               const float* __restrict__ scale,
                               float* __restrict__ out, int M, int N) {
    int t = blockIdx.x * blockDim.x + threadIdx.x;
    if (t >= M * N / 4) return;
    float4 s = make_float4(0.f, 0.f, 0.f, 0.f);
#pragma unroll
    for (int z = 0; z < NSPLIT; z++) {
        float4 v = ((const float4*)(part + (size_t)z * M * N))[t];
        s.x += v.x; s.y += v.y; s.z += v.z; s.w += v.w;
    }
    int row = (t * 4) / N;
    float r = 1.f / scale[row];
    s.x *= r; s.y *= r; s.z *= r; s.w *= r;
    ((float4*)out)[t] = s;
}

__global__ void final_k(const float* __restrict__ Wg1, const float* __restrict__ bg1,
                        const float* __restrict__ Wg2, const float* __restrict__ bg2,
                        const float* __restrict__ Wg3, const float* __restrict__ bg3,
                        float* __restrict__ outv, float* __restrict__ outy) {
    __shared__ float vcat[2 * Hn];
    __shared__ float y1[Hn];
    __shared__ float y2[Hn];
    int t = threadIdx.x;  // 1024
    vcat[t] = g_v[t];
    outv[t] = g_v[t];
    __syncthreads();
    if (t < Hn) {
        float s = bg1[t];
        for (int k = 0; k < 2 * Hn; k++) s += vcat[k] * Wg1[t * 2 * Hn + k];
        y1[t] = fmaxf(s, 0.f);
    }
    __syncthreads();
    if (t < Hn) {
        float s = bg2[t];
        for (int k = 0; k < Hn; k++) s += y1[k] * Wg2[t * Hn + k];
        y2[t] = fmaxf(s, 0.f);
    }
    __syncthreads();
    if (t == 0) {
        float z[3];
        float mx = -1e30f;
        for (int c = 0; c < 3; c++) {
            float s = bg3[c];
            for (int k = 0; k < Hn; k++) s += y2[k] * Wg3[c * Hn + k];
            z[c] = s;
            mx = fmaxf(mx, z[c]);
        }
        float se = 0.f;
        for (int c = 0; c < 3; c++) { z[c] = expf(z[c] - mx); se += z[c]; }
        for (int c = 0; c < 3; c++) outy[c] = z[c] / se;
    }
}

// ---------------- launch --------------------------------------------------
static int smem_bytes(bool at) {
    int aw = at ? 32 * 136 : 128 * 36;
    return 3 * (aw + 128 * 36) * 4;
}

extern "C" void kernel_launch(void* const* d_in, const int* in_sizes, int n_in,
                              void* d_out, int out_size) {
    const int*   p_idx = (const int*)d_in[0];
    const int*   h_idx = (const int*)d_in[1];
    const float* emb   = (const float*)d_in[2];
    const float* W_a1  = (const float*)d_in[3];
    const float* b_a1  = (const float*)d_in[4];
    const float* W_a2  = (const float*)d_in[5];
    const float* b_a2  = (const float*)d_in[6];
    const float* W_c1  = (const float*)d_in[7];
    const float* b_c1  = (const float*)d_in[8];
    const float* W_c2  = (const float*)d_in[9];
    const float* b_c2  = (const float*)d_in[10];
    const float* W_g1  = (const float*)d_in[11];
    const float* b_g1  = (const float*)d_in[12];
    const float* W_g2  = (const float*)d_in[13];
    const float* b_g2  = (const float*)d_in[14];
    const float* W_g3  = (const float*)d_in[15];
    const float* b_g3  = (const float*)d_in[16];

    float* out      = (float*)d_out;
    float* outE     = out;
    float* outBeta  = outE + (size_t)LPn * LHn;
    float* outAlpha = outBeta + (size_t)LPn * Dn;
    float* outV     = outAlpha + (size_t)LHn * Dn;
    float* outY     = outV + 2 * Hn;

    float *embp, *t1, *fa, *t2, *cat, *part, *eik, *ekj, *v;
    float *wa1, *wa2, *wc1, *wc2, *fhT, *hembT, *pembT;
    cudaGetSymbolAddress((void**)&embp, g_emb);
    cudaGetSymbolAddress((void**)&t1, g_t1);
    cudaGetSymbolAddress((void**)&fa, g_fa);
    cudaGetSymbolAddress((void**)&t2, g_t2);
    cudaGetSymbolAddress((void**)&cat, g_cat);
    cudaGetSymbolAddress((void**)&part, g_part);
    cudaGetSymbolAddress((void**)&eik, g_eik);
    cudaGetSymbolAddress((void**)&ekj, g_ekj);
    cudaGetSymbolAddress((void**)&v, g_v);
    cudaGetSymbolAddress((void**)&wa1, g_wa1);
    cudaGetSymbolAddress((void**)&wa2, g_wa2);
    cudaGetSymbolAddress((void**)&wc1, g_wc1);
    cudaGetSymbolAddress((void**)&wc2, g_wc2);
    cudaGetSymbolAddress((void**)&fhT, g_fhT);
    cudaGetSymbolAddress((void**)&hembT, g_hembT);
    cudaGetSymbolAddress((void**)&pembT, g_pembT);

    const int SM_D = smem_bytes(false);
    const int SM_T = smem_bytes(true);
    cudaFuncSetAttribute(tgemm<false, 1, true, false>,  cudaFuncAttributeMaxDynamicSharedMemorySize, SM_D);
    cudaFuncSetAttribute(tgemm<false, 1, false, false>, cudaFuncAttributeMaxDynamicSharedMemorySize, SM_D);
    cudaFuncSetAttribute(tgemm<false, 0, true, false>,  cudaFuncAttributeMaxDynamicSharedMemorySize, SM_D);
    cudaFuncSetAttribute(tgemm<false, 0, false, true>,  cudaFuncAttributeMaxDynamicSharedMemorySize, SM_D);
    cudaFuncSetAttribute(tgemm<true, 0, false, true>,   cudaFuncAttributeMaxDynamicSharedMemorySize, SM_T);

    const int TB = 256;
    const int MT = LPn + LHn;  // 8192

    // gathers (rounded), weight conversion, transposes of emb halves, zeroing
    gather4_k<<<(LPn * (Dn / 4) + TB - 1) / TB, TB>>>(p_idx, emb, embp, LPn);
    gather4_k<<<(LHn * (Dn / 4) + TB - 1) / TB, TB>>>(h_idx, emb, embp + (size_t)LPn * Dn, LHn);
    cvtw_k<<<(Hn * Dn + TB - 1) / TB, TB>>>(W_a1, wa1, Hn * Dn);
    cvtw_k<<<(Hn * Hn + TB - 1) / TB, TB>>>(W_a2, wa2, Hn * Hn);
    cvtw_k<<<(Hn * 2 * Dn + TB - 1) / TB, TB>>>(W_c1, wc1, Hn * 2 * Dn);
    cvtw_k<<<(Hn * Hn + TB - 1) / TB, TB>>>(W_c2, wc2, Hn * Hn);
    transpose_k<<<dim3((Dn + 31) / 32, LHn / 32), dim3(32, 8)>>>(embp + (size_t)LPn * Dn, hembT, LHn, Dn);
    transpose_k<<<dim3((Dn + 31) / 32, LPn / 32), dim3(32, 8)>>>(embp, pembT, LPn, Dn);
    zero_k<<<16, 256>>>();

    // attend (merged p|h)
    tgemm<false, 1, true, false><<<dim3(Hn / 128, MT / 128), 256, SM_D>>>(
        embp, Dn, wa1, Dn, b_a1, t1, Hn, MT, Hn, Dn, 0);
    tgemm<false, 1, true, false><<<dim3(Hn / 128, MT / 128), 256, SM_D>>>(
        t1, Hn, wa2, Hn, b_a2, fa, Hn, MT, Hn, Hn, 0);

    // transpose reshape(fh,[H,LH]) -> fhT [LH, H]
    transpose_k<<<dim3(LHn / 32, Hn / 32), dim3(32, 8)>>>(fa + (size_t)LPn * Hn, fhT, Hn, LHn);

    // E = fp @ reshape(fh) : B = fhT (W-form [4096, 512])
    tgemm<false, 0, true, false><<<dim3(LHn / 128, LPn / 128), 256, SM_D>>>(
        fa, Hn, fhT, Hn, nullptr, outE, LHn, LPn, LHn, Hn, 0);

    rowsum_k<<<LPn / 8, 256>>>(outE, eik);
    colsum_acc_k<<<dim3(LHn / 256, 32), 256>>>(outE, ekj, LHn, LPn / 32);

    // beta partials (split-K): A=E, B = hembT (W-form [300, 4096])
    tgemm<false, 0, false, true>
        <<<dim3((Dn + 127) / 128, LPn / 128, NSPLIT), 256, SM_D>>>(
        outE, LHn, hembT, LHn, nullptr, part, Dn, LPn, Dn, LHn, LHn / NSPLIT);
    reduce_scale_k<<<(LPn * Dn / 4 + TB - 1) / TB, TB>>>(part, eik, outBeta, LPn, Dn);

    // alpha partials (split-K): A = E^T (scalar path), B = pembT
    tgemm<true, 0, false, true>
        <<<dim3((Dn + 127) / 128, LHn / 128, NSPLIT), 256, SM_T>>>(
        outE, LHn, pembT, LPn, nullptr, part, Dn, LHn, Dn, LPn, LPn / NSPLIT);
    reduce_scale_k<<<(LHn * Dn / 4 + TB - 1) / TB, TB>>>(part, ekj, outAlpha, LHn, Dn);

    // comp (merged)
    concat_k<<<(MT * (2 * Dn / 4) + TB - 1) / TB, TB>>>(outBeta, outAlpha, cat);
    tgemm<false, 1, true, false><<<dim3(Hn / 128, MT / 128), 256, SM_D>>>(
        cat, 2 * Dn, wc1, 2 * Dn, b_c1, t1, Hn, MT, Hn, 2 * Dn, 0);
    tgemm<false, 1, false, false><<<dim3(Hn / 128, MT / 128), 256, SM_D>>>(
        t1, Hn, wc2, Hn, b_c2, t2, Hn, MT, Hn, Hn, 0);
    colsum_acc_k<<<dim3(Hn / 256, 32), 256>>>(t2, v, Hn, LPn / 32);
    colsum_acc_k<<<dim3(Hn / 256, 32), 256>>>(t2 + (size_t)LPn * Hn, v + Hn, Hn, LHn / 32);

    final_k<<<1, 1024>>>(W_g1, b_g1, W_g2, b_g2, W_g3, b_g3, outV, outY);
}

// round 7
// speedup vs baseline: 1.1319x; 1.1319x over previous
#include <cuda_runtime.h>
#include <cstdint>

#define LPn 4096
#define LHn 4096
#define Dn 300
#define Hn 512
#define NSPL 8

// ---------------- scratch (device globals; no allocation allowed) ----------
__device__ float g_emb[(LPn + LHn) * Dn];  // p rows then h rows (tf32-rounded)
__device__ float g_t1[(LPn + LHn) * Hn];
__device__ float g_fa[(LPn + LHn) * Hn];   // attend out: fp | fh (rounded)
__device__ float g_t2[(LPn + LHn) * Hn];
__device__ float g_cat[(LPn + LHn) * 2 * Dn];
__device__ float g_part[NSPL * Dn * Hn];   // split-K partials for G1/G2
__device__ float g_G1[Dn * Hn];            // G1T [300, 512]
__device__ float g_G2[Dn * Hn];            // G2T [300, 512]
__device__ float g_eik[LPn];
__device__ float g_ekj[LHn];
__device__ float g_v[2 * Hn];
__device__ float g_wa1[Hn * Dn];
__device__ float g_wa2[Hn * Hn];
__device__ float g_wc1[Hn * 2 * Dn];
__device__ float g_wc2[Hn * Hn];
__device__ float g_fhT[LHn * Hn];    // transpose of reshape(fh,[H,LH]) -> [LH, H]
__device__ float g_fpT[Hn * LPn];    // fp^T [512, 4096]
__device__ float g_hembT[Dn * LHn];  // [300, 4096]
__device__ float g_pembT[Dn * LPn];  // [300, 4096]

// ---------------- helpers ---------------------------------------------------
__device__ __forceinline__ uint32_t f2tf(float x) {
    uint32_t u;
    asm("cvt.rna.tf32.f32 %0, %1;" : "=r"(u) : "f"(x));
    return u;
}
__device__ __forceinline__ float roundtf(float x) { return __uint_as_float(f2tf(x)); }

__device__ __forceinline__ void cpa16(uint32_t saddr, const float* g, uint32_t vb) {
    asm volatile("cp.async.cg.shared.global [%0], [%1], 16, %2;"
                 ::"r"(saddr), "l"(g), "r"(vb));
}
#define CP_COMMIT() asm volatile("cp.async.commit_group;" ::: "memory")
#define CP_WAIT1() asm volatile("cp.async.wait_group 1;" ::: "memory")

__device__ __forceinline__ void mma8(float* c, const uint32_t* a, uint32_t b0, uint32_t b1) {
    asm volatile(
        "mma.sync.aligned.m16n8k8.row.col.f32.tf32.tf32.f32 "
        "{%0,%1,%2,%3}, {%4,%5,%6,%7}, {%8,%9}, {%0,%1,%2,%3};"
        : "+f"(c[0]), "+f"(c[1]), "+f"(c[2]), "+f"(c[3])
        : "r"(a[0]), "r"(a[1]), "r"(a[2]), "r"(a[3]), "r"(b0), "r"(b1));
}

__device__ __forceinline__ void ldm4(uint32_t* r, uint32_t addr) {
    asm volatile("ldmatrix.sync.aligned.m8n8.x4.shared.b16 {%0,%1,%2,%3}, [%4];"
                 : "=r"(r[0]), "=r"(r[1]), "=r"(r[2]), "=r"(r[3]) : "r"(addr));
}

// direct: src row-major [rows, ld]; chunk cols [k0,k0+32) -> smem [r][k] stride 36
__device__ __forceinline__ void loadDirectAsync(const float* __restrict__ src, int ld,
                                                int row0, int rlim, int k0, int kend,
                                                uint32_t saddr) {
    int t = threadIdx.x;
    int r = t >> 1, half = (t & 1) * 16;
    int gr = row0 + r;
    bool rok = gr < rlim;
    const float* p = src + (size_t)(rok ? gr : row0) * ld + k0 + half;
    uint32_t sa = saddr + (uint32_t)(r * 36 + half) * 4;
#pragma unroll
    for (int j = 0; j < 4; j++) {
        int gk = k0 + half + j * 4;
        uint32_t vb = (rok && gk + 3 < kend) ? 16u : 0u;
        cpa16(sa + j * 16, p + j * 4, vb);
    }
}

// trans: src row-major [Ktot, ld]; rows [k0,k0+32), cols [c0,c0+128) -> smem [k][c] stride 136
__device__ __forceinline__ void loadTransAsync(const float* __restrict__ src, int ld,
                                               int c0, int clim, int k0, int kend,
                                               uint32_t saddr) {
    int t = threadIdx.x;
    int k = t >> 3;
    int gk = k0 + k;
    bool kok = gk < kend;
    const float* p = src + (size_t)(kok ? gk : k0) * ld + c0;
    uint32_t sa = saddr + (uint32_t)(k * 136) * 4;
#pragma unroll
    for (int j = 0; j < 4; j++) {
        int c = ((t & 7) + j * 8) * 4;
        uint32_t vb = (kok && c0 + c + 3 < clim) ? 16u : 0u;
        cpa16(sa + (uint32_t)c * 4, p + c, vb);
    }
}

// ---------------- mma.sync tf32 GEMM, cp.async 3-stage, ldmatrix -----------
// C[M,N] = A @ B.
//   AT=0: A row-major [M,K] (ldmatrix). AT=1: A[m,k]=src[k*lda+m] (scalar LDS).
//   B is ALWAYS W-form [N,K] row-major -> smem [n][k] stride 36 (ldmatrix).
// EPI: 0 none; 1 bias+relu (aux=bias[N]); 2 row-scale by 1/aux[row].
// ROUND: tf32-round stores. SPLITK: blockIdx.z picks K range, C += z*M*ldc.
template <bool AT, int EPI, bool ROUND, bool SPLITK>
__global__ void __launch_bounds__(256, 2)
tgemm(const float* __restrict__ A, int lda,
      const float* __restrict__ B, int ldb,
      const float* __restrict__ aux,
      float* __restrict__ C, int ldc,
      int M, int N, int K, int Ksub) {
    constexpr int AW = AT ? 32 * 136 : 128 * 36;
    constexpr int BW = 128 * 36;
    constexpr int STW = AW + BW;
    extern __shared__ uint32_t sm[];
    const uint32_t sbase = (uint32_t)__cvta_generic_to_shared(sm);

    const int tid = threadIdx.x, wid = tid >> 5, lane = tid & 31;
    const int gid = lane >> 2, tig = lane & 3;
    const int wm = wid >> 1, wn = wid & 1;
    const int bm = blockIdx.y * 128, bn = blockIdx.x * 128;

    int k_off = 0, Kloc = K;
    if (SPLITK) {
        k_off = blockIdx.z * Ksub;
        Kloc = Ksub;
        C += (size_t)blockIdx.z * M * ldc;
    }
    const int kend = k_off + Kloc;
    const int NC = (Kloc + 31) / 32;

    float acc[2][8][4];
#pragma unroll
    for (int i = 0; i < 2; i++)
#pragma unroll
        for (int j = 0; j < 8; j++)
#pragma unroll
            for (int q = 0; q < 4; q++) acc[i][j][q] = 0.f;

    const uint32_t a_lm_off =
        (uint32_t)((wm * 32 + (lane & 15)) * 36 + ((lane >> 4) << 2)) * 4;
    const uint32_t b_lm_off =
        (uint32_t)AW * 4 +
        (uint32_t)((wn * 64 + (lane & 7) + ((lane >> 4) << 3)) * 36 + (((lane >> 3) & 1) << 2)) * 4;

#pragma unroll
    for (int pc = 0; pc < 2; pc++) {
        uint32_t sA = sbase + (uint32_t)(pc * STW) * 4;
        uint32_t sB = sA + (uint32_t)AW * 4;
        int k0 = k_off + pc * 32;
        if (AT) loadTransAsync(A, lda, bm, M, k0, kend, sA);
        else    loadDirectAsync(A, lda, bm, M, k0, kend, sA);
        loadDirectAsync(B, ldb, bn, N, k0, kend, sB);
        CP_COMMIT();
    }

    for (int kc = 0; kc < NC; kc++) {
        CP_WAIT1();
        __syncthreads();
        if (kc + 2 < NC) {
            int st = (kc + 2) % 3;
            int k0 = k_off + (kc + 2) * 32;
            uint32_t sA = sbase + (uint32_t)(st * STW) * 4;
            uint32_t sB = sA + (uint32_t)AW * 4;
            if (AT) loadTransAsync(A, lda, bm, M, k0, kend, sA);
            else    loadDirectAsync(A, lda, bm, M, k0, kend, sA);
            loadDirectAsync(B, ldb, bn, N, k0, kend, sB);
        }
        CP_COMMIT();

        const uint32_t stoff = (uint32_t)((kc % 3) * STW) * 4;
        const uint32_t* SA_p = sm + (kc % 3) * STW;
#pragma unroll
        for (int kk = 0; kk < 4; kk++) {
            int k8 = kk * 8;
            uint32_t a[2][4];
            if (AT) {
#pragma unroll
                for (int mi = 0; mi < 2; mi++) {
                    int m0 = wm * 32 + mi * 16;
                    a[mi][0] = SA_p[(k8 + tig) * 136 + m0 + gid];
                    a[mi][1] = SA_p[(k8 + tig) * 136 + m0 + gid + 8];
                    a[mi][2] = SA_p[(k8 + tig + 4) * 136 + m0 + gid];
                    a[mi][3] = SA_p[(k8 + tig + 4) * 136 + m0 + gid + 8];
                }
            } else {
                uint32_t ab = sbase + stoff + a_lm_off + (uint32_t)k8 * 4;
                ldm4(a[0], ab);
                ldm4(a[1], ab + 16 * 36 * 4);
            }
            uint32_t b[8][2];
#pragma unroll
            for (int nj = 0; nj < 4; nj++) {
                uint32_t r[4];
                ldm4(r, sbase + stoff + b_lm_off + (uint32_t)(nj * 16 * 36 + k8) * 4);
                b[2 * nj][0] = r[0]; b[2 * nj][1] = r[1];
                b[2 * nj + 1][0] = r[2]; b[2 * nj + 1][1] = r[3];
            }
#pragma unroll
            for (int ni = 0; ni < 8; ni++) {
                mma8(acc[0][ni], a[0], b[ni][0], b[ni][1]);
                mma8(acc[1][ni], a[1], b[ni][0], b[ni][1]);
            }
        }
    }

    // epilogue (row-guarded)
#pragma unroll
    for (int mi = 0; mi < 2; mi++) {
        int r0 = bm + wm * 32 + mi * 16 + gid;
        float s0 = 1.f, s1 = 1.f;
        if (EPI == 2) {
            if (r0 < M) s0 = 1.f / aux[r0];
            if (r0 + 8 < M) s1 = 1.f / aux[r0 + 8];
        }
#pragma unroll
        for (int ni = 0; ni < 8; ni++) {
            int col = bn + wn * 64 + ni * 8 + tig * 2;
            if (col >= N) continue;
            float v0 = acc[mi][ni][0], v1 = acc[mi][ni][1];
            float v2 = acc[mi][ni][2], v3 = acc[mi][ni][3];
            if (EPI == 1) {
                float bi0 = aux[col];
                float bi1 = (col + 1 < N) ? aux[col + 1] : 0.f;
                v0 = fmaxf(v0 + bi0, 0.f); v1 = fmaxf(v1 + bi1, 0.f);
                v2 = fmaxf(v2 + bi0, 0.f); v3 = fmaxf(v3 + bi1, 0.f);
            }
            if (EPI == 2) { v0 *= s0; v1 *= s0; v2 *= s1; v3 *= s1; }
            if (ROUND) {
                v0 = roundtf(v0); v1 = roundtf(v1);
                v2 = roundtf(v2); v3 = roundtf(v3);
            }
            float* c0p = C + (size_t)r0 * ldc + col;
            float* c1p = C + (size_t)(r0 + 8) * ldc + col;
            if (col + 1 < N) {
                if (r0 < M) *(float2*)c0p = make_float2(v0, v1);
                if (r0 + 8 < M) *(float2*)c1p = make_float2(v2, v3);
            } else {
                if (r0 < M) *c0p = v0;
                if (r0 + 8 < M) *c1p = v2;
            }
        }
    }
}

// ---------------- small kernels -------------------------------------------
__global__ void gatherall_k(const int* __restrict__ p_idx, const int* __restrict__ h_idx,
                            const float* __restrict__ emb, float* __restrict__ dst) {
    int t = blockIdx.x * blockDim.x + threadIdx.x;
    if (t >= (LPn + LHn) * (Dn / 4)) return;
    int r = t / (Dn / 4), c = t - r * (Dn / 4);
    int ix = (r < LPn) ? p_idx[r] : h_idx[r - LPn];
    float4 v = ((const float4*)(emb + (size_t)ix * Dn))[c];
    v.x = roundtf(v.x); v.y = roundtf(v.y);
    v.z = roundtf(v.z); v.w = roundtf(v.w);
    ((float4*)dst)[t] = v;
}

__global__ void cvtall_k(const float* __restrict__ wa1, const float* __restrict__ wa2,
                         const float* __restrict__ wc1, const float* __restrict__ wc2) {
    int t = blockIdx.x * blockDim.x + threadIdx.x;
    if (t < Hn * Dn) g_wa1[t] = roundtf(wa1[t]);
    if (t < Hn * Hn) g_wa2[t] = roundtf(wa2[t]);
    if (t < Hn * 2 * Dn) g_wc1[t] = roundtf(wc1[t]);
    if (t < Hn * Hn) g_wc2[t] = roundtf(wc2[t]);
}

// dst[c][r] = src[r][c]; src [R, C] row-major
__global__ void transpose_k(const float* __restrict__ src, float* __restrict__ dst,
                            int R, int C) {
    __shared__ float tile[32][33];
    int c = blockIdx.x * 32 + threadIdx.x;
    int r = blockIdx.y * 32 + threadIdx.y;
#pragma unroll
    for (int i = 0; i < 32; i += 8)
        if (r + i < R && c < C) tile[threadIdx.y + i][threadIdx.x] = src[(size_t)(r + i) * C + c];
    __syncthreads();
    int c2 = blockIdx.y * 32 + threadIdx.x;
    int r2 = blockIdx.x * 32 + threadIdx.y;
#pragma unroll
    for (int i = 0; i < 32; i += 8)
        if (r2 + i < C && c2 < R) dst[(size_t)(r2 + i) * R + c2] = tile[threadIdx.x][threadIdx.y + i];
}

__global__ void zero_k() {
    int t = blockIdx.x * blockDim.x + threadIdx.x;
    if (t < LHn) g_ekj[t] = 0.f;
    if (t < 2 * Hn) g_v[t] = 0.f;
}

__global__ void rowsum_k(const float* __restrict__ E, float* __restrict__ out) {
    int row = blockIdx.x * (blockDim.x / 32) + (threadIdx.x >> 5);
    int lane = threadIdx.x & 31;
    const float4* p = (const float4*)(E + (size_t)row * LHn);
    float s = 0.f;
    for (int j = lane; j < LHn / 4; j += 32) {
        float4 v = p[j];
        s += (v.x + v.y) + (v.z + v.w);
    }
#pragma unroll
    for (int o = 16; o; o >>= 1) s += __shfl_xor_sync(0xffffffffu, s, o);
    if (lane == 0) out[row] = s;
}

__global__ void colsum_acc_k(const float* __restrict__ X, float* __restrict__ out,
                             int cols, int rows_per_blk) {
    int col = blockIdx.x * blockDim.x + threadIdx.x;
    if (col >= cols) return;
    long r0 = (long)blockIdx.y * rows_per_blk;
    float s = 0.f;
    for (long r = r0; r < r0 + rows_per_blk; r++) s += X[r * cols + col];
    atomicAdd(&out[col], s);
}

__global__ void concat_k(const float* __restrict__ beta, const float* __restrict__ alpha,
                         float* __restrict__ dst) {
    int t = blockIdx.x * blockDim.x + threadIdx.x;
    if (t >= (LPn + LHn) * (2 * Dn / 4)) return;
    int R = t / (2 * Dn / 4), c4 = t - R * (2 * Dn / 4);
    float4 v;
    if (c4 < Dn / 4) {
        v = ((const float4*)(g_emb + (size_t)R * Dn))[c4];
    } else {
        const float* src = (R < LPn) ? (beta + (size_t)R * Dn)
                                     : (alpha + (size_t)(R - LPn) * Dn);
        v = ((const float4*)src)[c4 - Dn / 4];
        v.x = roundtf(v.x); v.y = roundtf(v.y);
        v.z = roundtf(v.z); v.w = roundtf(v.w);
    }
    ((float4*)dst)[t] = v;
}

// sum NSPL partials -> out (tf32-rounded), size M*N
__global__ void reduce_k(const float* __restrict__ part, float* __restrict__ out, int MN) {
    int t = blockIdx.x * blockDim.x + threadIdx.x;
    if (t >= MN / 4) return;
    float4 s = make_float4(0.f, 0.f, 0.f, 0.f);
#pragma unroll
    for (int z = 0; z < NSPL; z++) {
        float4 v = ((const float4*)(part + (size_t)z * MN))[t];
        s.x += v.x; s.y += v.y; s.z += v.z; s.w += v.w;
    }
    s.x = roundtf(s.x); s.y = roundtf(s.y);
    s.z = roundtf(s.z); s.w = roundtf(s.w);
    ((float4*)out)[t] = s;
}

__global__ void final_k(const float* __restrict__ Wg1, const float* __restrict__ bg1,
                        const float* __restrict__ Wg2, const float* __restrict__ bg2,
                        const float* __restrict__ Wg3, const float* __restrict__ bg3,
                        float* __restrict__ outv, float* __restrict__ outy) {
    __shared__ float vcat[2 * Hn];
    __shared__ float y1[Hn];
    __shared__ float y2[Hn];
    int t = threadIdx.x;  // 1024
    vcat[t] = g_v[t];
    outv[t] = g_v[t];
    __syncthreads();
    if (t < Hn) {
        float s = bg1[t];
        for (int k = 0; k < 2 * Hn; k++) s += vcat[k] * Wg1[t * 2 * Hn + k];
        y1[t] = fmaxf(s, 0.f);
    }
    __syncthreads();
    if (t < Hn) {
        float s = bg2[t];
        for (int k = 0; k < Hn; k++) s += y1[k] * Wg2[t * Hn + k];
        y2[t] = fmaxf(s, 0.f);
    }
    __syncthreads();
    if (t == 0) {
        float z[3];
        float mx = -1e30f;
        for (int c = 0; c < 3; c++) {
            float s = bg3[c];
            for (int k = 0; k < Hn; k++) s += y2[k] * Wg3[c * Hn + k];
            z[c] = s;
            mx = fmaxf(mx, z[c]);
        }
        float se = 0.f;
        for (int c = 0; c < 3; c++) { z[c] = expf(z[c] - mx); se += z[c]; }
        for (int c = 0; c < 3; c++) outy[c] = z[c] / se;
    }
}

// ---------------- launch --------------------------------------------------
static int smem_bytes(bool at) {
    int aw = at ? 32 * 136 : 128 * 36;
    return 3 * (aw + 128 * 36) * 4;
}

extern "C" void kernel_launch(void* const* d_in, const int* in_sizes, int n_in,
                              void* d_out, int out_size) {
    const int*   p_idx = (const int*)d_in[0];
    const int*   h_idx = (const int*)d_in[1];
    const float* emb   = (const float*)d_in[2];
    const float* W_a1  = (const float*)d_in[3];
    const float* b_a1  = (const float*)d_in[4];
    const float* W_a2  = (const float*)d_in[5];
    const float* b_a2  = (const float*)d_in[6];
    const float* W_c1  = (const float*)d_in[7];
    const float* b_c1  = (const float*)d_in[8];
    const float* W_c2  = (const float*)d_in[9];
    const float* b_c2  = (const float*)d_in[10];
    const float* W_g1  = (const float*)d_in[11];
    const float* b_g1  = (const float*)d_in[12];
    const float* W_g2  = (const float*)d_in[13];
    const float* b_g2  = (const float*)d_in[14];
    const float* W_g3  = (const float*)d_in[15];
    const float* b_g3  = (const float*)d_in[16];

    float* out      = (float*)d_out;
    float* outE     = out;
    float* outBeta  = outE + (size_t)LPn * LHn;
    float* outAlpha = outBeta + (size_t)LPn * Dn;
    float* outV     = outAlpha + (size_t)LHn * Dn;
    float* outY     = outV + 2 * Hn;

    float *embp, *t1, *fa, *t2, *cat, *part, *G1, *G2, *eik, *ekj, *v;
    float *wa1, *wa2, *wc1, *wc2, *fhT, *fpT, *hembT, *pembT;
    cudaGetSymbolAddress((void**)&embp, g_emb);
    cudaGetSymbolAddress((void**)&t1, g_t1);
    cudaGetSymbolAddress((void**)&fa, g_fa);
    cudaGetSymbolAddress((void**)&t2, g_t2);
    cudaGetSymbolAddress((void**)&cat, g_cat);
    cudaGetSymbolAddress((void**)&part, g_part);
    cudaGetSymbolAddress((void**)&G1, g_G1);
    cudaGetSymbolAddress((void**)&G2, g_G2);
    cudaGetSymbolAddress((void**)&eik, g_eik);
    cudaGetSymbolAddress((void**)&ekj, g_ekj);
    cudaGetSymbolAddress((void**)&v, g_v);
    cudaGetSymbolAddress((void**)&wa1, g_wa1);
    cudaGetSymbolAddress((void**)&wa2, g_wa2);
    cudaGetSymbolAddress((void**)&wc1, g_wc1);
    cudaGetSymbolAddress((void**)&wc2, g_wc2);
    cudaGetSymbolAddress((void**)&fhT, g_fhT);
    cudaGetSymbolAddress((void**)&fpT, g_fpT);
    cudaGetSymbolAddress((void**)&hembT, g_hembT);
    cudaGetSymbolAddress((void**)&pembT, g_pembT);

    const int SM_D = smem_bytes(false);
    const int SM_T = smem_bytes(true);
    cudaFuncSetAttribute(tgemm<false, 1, true, false>,  cudaFuncAttributeMaxDynamicSharedMemorySize, SM_D);
    cudaFuncSetAttribute(tgemm<false, 1, false, false>, cudaFuncAttributeMaxDynamicSharedMemorySize, SM_D);
    cudaFuncSetAttribute(tgemm<false, 0, true, false>,  cudaFuncAttributeMaxDynamicSharedMemorySize, SM_D);
    cudaFuncSetAttribute(tgemm<false, 0, false, true>,  cudaFuncAttributeMaxDynamicSharedMemorySize, SM_D);
    cudaFuncSetAttribute(tgemm<false, 2, false, false>, cudaFuncAttributeMaxDynamicSharedMemorySize, SM_D);
    cudaFuncSetAttribute(tgemm<true, 2, false, false>,  cudaFuncAttributeMaxDynamicSharedMemorySize, SM_T);

    const int TB = 256;
    const int MT = LPn + LHn;  // 8192
    const float* fhR = fa + (size_t)LPn * Hn;  // reshape(fh,[H,LH]) = [512, 4096] row-major

    // gathers + weight rounding + emb transposes + zeroing
    gatherall_k<<<(MT * (Dn / 4) + TB - 1) / TB, TB>>>(p_idx, h_idx, emb, embp);
    cvtall_k<<<(Hn * 2 * Dn + TB - 1) / TB, TB>>>(W_a1, W_a2, W_c1, W_c2);
    transpose_k<<<dim3((Dn + 31) / 32, LHn / 32), dim3(32, 8)>>>(embp + (size_t)LPn * Dn, hembT, LHn, Dn);
    transpose_k<<<dim3((Dn + 31) / 32, LPn / 32), dim3(32, 8)>>>(embp, pembT, LPn, Dn);
    zero_k<<<16, 256>>>();

    // attend (merged p|h)
    tgemm<false, 1, true, false><<<dim3(Hn / 128, MT / 128), 256, SM_D>>>(
        embp, Dn, wa1, Dn, b_a1, t1, Hn, MT, Hn, Dn, 0);
    tgemm<false, 1, true, false><<<dim3(Hn / 128, MT / 128), 256, SM_D>>>(
        t1, Hn, wa2, Hn, b_a2, fa, Hn, MT, Hn, Hn, 0);

    // transposes of attend outputs
    transpose_k<<<dim3(LHn / 32, Hn / 32), dim3(32, 8)>>>(fhR, fhT, Hn, LHn);   // fhT [4096, 512]
    transpose_k<<<dim3(Hn / 32, LPn / 32), dim3(32, 8)>>>(fa, fpT, LPn, Hn);    // fpT [512, 4096]

    // E = fp @ fhR : B = fhT (W-form [4096, 512])
    tgemm<false, 0, true, false><<<dim3(LHn / 128, LPn / 128), 256, SM_D>>>(
        fa, Hn, fhT, Hn, nullptr, outE, LHn, LPn, LHn, Hn, 0);

    rowsum_k<<<LPn / 8, 256>>>(outE, eik);
    colsum_acc_k<<<dim3(LHn / 256, 32), 256>>>(outE, ekj, LHn, LPn / 32);

    // G1T [300,512] = hembT @ fhR^T : A = hembT direct, B W-form = fhR [512, 4096]
    tgemm<false, 0, false, true><<<dim3(4, 3, NSPL), 256, SM_D>>>(
        hembT, LHn, fhR, LHn, nullptr, part, Hn, Dn, Hn, LHn, LHn / NSPL);
    reduce_k<<<(Dn * Hn / 4 + TB - 1) / TB, TB>>>(part, G1, Dn * Hn);

    // G2T [300,512] = pembT @ fp : A = pembT direct, B W-form = fpT [512, 4096]
    tgemm<false, 0, false, true><<<dim3(4, 3, NSPL), 256, SM_D>>>(
        pembT, LPn, fpT, LPn, nullptr, part, Hn, Dn, Hn, LPn, LPn / NSPL);
    reduce_k<<<(Dn * Hn / 4 + TB - 1) / TB, TB>>>(part, G2, Dn * Hn);

    // beta = diag(1/eik) * fp @ G1 : A = fp direct [4096,512], B W-form = G1T [300,512]
    tgemm<false, 2, false, false><<<dim3(3, LPn / 128), 256, SM_D>>>(
        fa, Hn, G1, Hn, eik, outBeta, Dn, LPn, Dn, Hn, 0);

    // alpha = diag(1/ekj) * fhR^T @ G2 : A = fhR AT-form (lda=4096), B W-form = G2T
    tgemm<true, 2, false, false><<<dim3(3, LHn / 128), 256, SM_T>>>(
        fhR, LHn, G2, Hn, ekj, outAlpha, Dn, LHn, Dn, Hn, 0);

    // comp (merged)
    concat_k<<<(MT * (2 * Dn / 4) + TB - 1) / TB, TB>>>(outBeta, outAlpha, cat);
    tgemm<false, 1, true, false><<<dim3(Hn / 128, MT / 128), 256, SM_D>>>(
        cat, 2 * Dn, wc1, 2 * Dn, b_c1, t1, Hn, MT, Hn, 2 * Dn, 0);
    tgemm<false, 1, false, false><<<dim3(Hn / 128, MT / 128), 256, SM_D>>>(
        t1, Hn, wc2, Hn, b_c2, t2, Hn, MT, Hn, Hn, 0);
    colsum_acc_k<<<dim3(Hn / 256, 32), 256>>>(t2, v, Hn, LPn / 32);
    colsum_acc_k<<<dim3(Hn / 256, 32), 256>>>(t2 + (size_t)LPn * Hn, v + Hn, Hn, LHn / 32);

    final_k<<<1, 1024>>>(W_g1, b_g1, W_g2, b_g2, W_g3, b_g3, outV, outY);
}

// round 8
// speedup vs baseline: 1.4321x; 1.2652x over previous
#include <cuda_runtime.h>
#include <cuda_fp16.h>
#include <cstdint>

#define LPn 4096
#define LHn 4096
#define Dn 300
#define Hn 512
#define NSPL 8
#define DP 304   // Dn padded to x8
#define CP 608   // 2*Dn padded to x8

// ---------------- scratch (device globals; no allocation allowed) ----------
__device__ __half g_embh[(LPn + LHn) * DP];   // p|h rows, fp16, zero-padded cols
__device__ __half g_embT[DP * (LPn + LHn)];   // transpose (rows 300..303 junk)
__device__ __half g_t1h[(LPn + LHn) * Hn];
__device__ __half g_fah[(LPn + LHn) * Hn];    // attend out fp|fh, fp16
__device__ __half g_fhT[LHn * Hn];            // transpose of reshape(fh,[H,LH])
__device__ __half g_fpT[Hn * LPn];            // fp^T
__device__ __half g_cath[(LPn + LHn) * CP];
__device__ __half g_G1h[Dn * Hn];
__device__ __half g_G2h[Dn * Hn];
__device__ __half g_wa1[Hn * DP];
__device__ __half g_wa2[Hn * Hn];
__device__ __half g_wc1[Hn * CP];
__device__ __half g_wc2[Hn * Hn];
__device__ float g_part[NSPL * Dn * Hn];
__device__ float g_t2[(LPn + LHn) * Hn];
__device__ float g_eik[LPn];
__device__ float g_ekj[LHn];
__device__ float g_v[2 * Hn];

// ---------------- helpers ---------------------------------------------------
__device__ __forceinline__ void cpa16(uint32_t saddr, const void* g, uint32_t vb) {
    asm volatile("cp.async.cg.shared.global [%0], [%1], 16, %2;"
                 ::"r"(saddr), "l"(g), "r"(vb));
}
#define CP_COMMIT() asm volatile("cp.async.commit_group;" ::: "memory")
#define CP_WAIT1() asm volatile("cp.async.wait_group 1;" ::: "memory")

__device__ __forceinline__ void mma16(float* c, const uint32_t* a, uint32_t b0, uint32_t b1) {
    asm volatile(
        "mma.sync.aligned.m16n8k16.row.col.f32.f16.f16.f32 "
        "{%0,%1,%2,%3}, {%4,%5,%6,%7}, {%8,%9}, {%0,%1,%2,%3};"
        : "+f"(c[0]), "+f"(c[1]), "+f"(c[2]), "+f"(c[3])
        : "r"(a[0]), "r"(a[1]), "r"(a[2]), "r"(a[3]), "r"(b0), "r"(b1));
}
__device__ __forceinline__ void ldm4(uint32_t* r, uint32_t addr) {
    asm volatile("ldmatrix.sync.aligned.m8n8.x4.shared.b16 {%0,%1,%2,%3}, [%4];"
                 : "=r"(r[0]), "=r"(r[1]), "=r"(r[2]), "=r"(r[3]) : "r"(addr));
}
__device__ __forceinline__ void ldm4t(uint32_t* r, uint32_t addr) {
    asm volatile("ldmatrix.sync.aligned.m8n8.x4.trans.shared.b16 {%0,%1,%2,%3}, [%4];"
                 : "=r"(r[0]), "=r"(r[1]), "=r"(r[2]), "=r"(r[3]) : "r"(addr));
}

// direct: src half [rows][ld]; chunk [k0,k0+64) -> smem [r][k] stride 72 halves
__device__ __forceinline__ void loadDirH(const __half* __restrict__ src, int ld,
                                         int row0, int rlim, int k0, int kend,
                                         uint32_t saddr) {
    int t = threadIdx.x;
    int r = t >> 1, kb = (t & 1) * 32;
    int gr = row0 + r;
    bool rok = gr < rlim;
    const __half* p = src + (size_t)(rok ? gr : row0) * ld + k0 + kb;
    uint32_t sa = saddr + (uint32_t)(r * 72 + kb) * 2;
#pragma unroll
    for (int j = 0; j < 4; j++) {
        int gk = k0 + kb + j * 8;
        uint32_t vb = (rok && gk + 8 <= kend) ? 16u : 0u;
        cpa16(sa + j * 16, p + j * 8, vb);
    }
}

// trans (AT): src half [Ktot][ld]; k rows [k0,k0+64), m cols [c0,c0+128) -> smem [k][m] stride 136
__device__ __forceinline__ void loadTransH(const __half* __restrict__ src, int ld,
                                           int c0, int clim, int k0, int kend,
                                           uint32_t saddr) {
    int t = threadIdx.x;
    int k = t >> 2;
    int gk = k0 + k;
    bool kok = gk < kend;
    const __half* p = src + (size_t)(kok ? gk : k0) * ld + c0;
    uint32_t sa = saddr + (uint32_t)(k * 136) * 2;
#pragma unroll
    for (int j = 0; j < 4; j++) {
        int moff = ((t & 3) * 4 + j) * 8;
        int gm = c0 + moff;
        uint32_t vb = (kok && gm + 8 <= clim) ? 16u : 0u;
        cpa16(sa + (uint32_t)moff * 2, p + moff, vb);
    }
}

// ---------------- fp16 mma GEMM, cp.async 3-stage, BK=64 -------------------
// C[M,N] = A @ B. AT=0: A [M,K] row-major. AT=1: A[m,k]=src[k*lda+m].
// B ALWAYS W-form [N,K] row-major. EPI: 0 none; 1 bias+relu; 2 row-scale 1/aux[row].
// OH: output half (else float). SPLITK: z picks K range, C += z*M*ldc.
template <bool AT, int EPI, bool OH, bool SPLITK>
__global__ void __launch_bounds__(256, 2)
hgemm(const __half* __restrict__ A, int lda,
      const __half* __restrict__ B, int ldb,
      const float* __restrict__ aux,
      void* __restrict__ Cv, int ldc,
      int M, int N, int K, int Ksub) {
    constexpr int AWH = AT ? 64 * 136 : 128 * 72;  // halves
    constexpr int BWH = 128 * 72;
    constexpr int STH = AWH + BWH;
    extern __shared__ __half smh[];
    const uint32_t sbase = (uint32_t)__cvta_generic_to_shared(smh);

    const int tid = threadIdx.x, wid = tid >> 5, lane = tid & 31;
    const int gid = lane >> 2, tig = lane & 3;
    const int wm = wid >> 1, wn = wid & 1;
    const int bm = blockIdx.y * 128, bn = blockIdx.x * 128;

    int k_off = 0, Kloc = K;
    if (SPLITK) {
        k_off = blockIdx.z * Ksub;
        Kloc = Ksub;
        Cv = (void*)((float*)Cv + (size_t)blockIdx.z * M * ldc);
    }
    const int kend = k_off + Kloc;
    const int NC = (Kloc + 63) / 64;

    float acc[2][8][4];
#pragma unroll
    for (int i = 0; i < 2; i++)
#pragma unroll
        for (int j = 0; j < 8; j++)
#pragma unroll
            for (int q = 0; q < 4; q++) acc[i][j][q] = 0.f;

    // ldmatrix per-thread base offsets (bytes within stage)
    uint32_t a_off;
    if (AT) {
        int krow = ((lane >> 4) << 3) + (lane & 7);
        int moff = ((lane >> 3) & 1) * 8;
        a_off = (uint32_t)(krow * 136 + wm * 32 + moff) * 2;
    } else {
        a_off = (uint32_t)((wm * 32 + (lane & 15)) * 72 + (lane >> 4) * 8) * 2;
    }
    const uint32_t b_off =
        (uint32_t)AWH * 2 +
        (uint32_t)((wn * 64 + ((lane >> 4) << 3) + (lane & 7)) * 72 + ((lane >> 3) & 1) * 8) * 2;

    // prologue: chunks 0,1
#pragma unroll
    for (int pc = 0; pc < 2; pc++) {
        uint32_t sA = sbase + (uint32_t)(pc * STH) * 2;
        uint32_t sB = sA + (uint32_t)AWH * 2;
        int k0 = k_off + pc * 64;
        if (AT) loadTransH(A, lda, bm, M, k0, kend, sA);
        else    loadDirH(A, lda, bm, M, k0, kend, sA);
        loadDirH(B, ldb, bn, N, k0, kend, sB);
        CP_COMMIT();
    }

    for (int kc = 0; kc < NC; kc++) {
        CP_WAIT1();
        __syncthreads();
        if (kc + 2 < NC) {
            int st = (kc + 2) % 3;
            int k0 = k_off + (kc + 2) * 64;
            uint32_t sA = sbase + (uint32_t)(st * STH) * 2;
            uint32_t sB = sA + (uint32_t)AWH * 2;
            if (AT) loadTransH(A, lda, bm, M, k0, kend, sA);
            else    loadDirH(A, lda, bm, M, k0, kend, sA);
            loadDirH(B, ldb, bn, N, k0, kend, sB);
        }
        CP_COMMIT();

        const uint32_t stoff = (uint32_t)((kc % 3) * STH) * 2;
#pragma unroll
        for (int kk = 0; kk < 4; kk++) {
            uint32_t a[2][4];
            if (AT) {
                uint32_t ab = sbase + stoff + a_off + (uint32_t)(kk * 16 * 136) * 2;
                ldm4t(a[0], ab);
                ldm4t(a[1], ab + 16 * 2);  // +16 m halves
            } else {
                uint32_t ab = sbase + stoff + a_off + (uint32_t)(kk * 16) * 2;
                ldm4(a[0], ab);
                ldm4(a[1], ab + (uint32_t)(16 * 72) * 2);
            }
            uint32_t b[8][2];
#pragma unroll
            for (int nj = 0; nj < 4; nj++) {
                uint32_t r[4];
                ldm4(r, sbase + stoff + b_off + (uint32_t)(nj * 16 * 72 + kk * 16) * 2);
                b[2 * nj][0] = r[0]; b[2 * nj][1] = r[1];
                b[2 * nj + 1][0] = r[2]; b[2 * nj + 1][1] = r[3];
            }
#pragma unroll
            for (int ni = 0; ni < 8; ni++) {
                mma16(acc[0][ni], a[0], b[ni][0], b[ni][1]);
                mma16(acc[1][ni], a[1], b[ni][0], b[ni][1]);
            }
        }
    }

    // epilogue
#pragma unroll
    for (int mi = 0; mi < 2; mi++) {
        int r0 = bm + wm * 32 + mi * 16 + gid;
        float s0 = 1.f, s1 = 1.f;
        if (EPI == 2) {
            if (r0 < M) s0 = 1.f / aux[r0];
            if (r0 + 8 < M) s1 = 1.f / aux[r0 + 8];
        }
#pragma unroll
        for (int ni = 0; ni < 8; ni++) {
            int col = bn + wn * 64 + ni * 8 + tig * 2;
            if (col >= N) continue;
            float v0 = acc[mi][ni][0], v1 = acc[mi][ni][1];
            float v2 = acc[mi][ni][2], v3 = acc[mi][ni][3];
            if (EPI == 1) {
                float bi0 = aux[col];
                float bi1 = (col + 1 < N) ? aux[col + 1] : 0.f;
                v0 = fmaxf(v0 + bi0, 0.f); v1 = fmaxf(v1 + bi1, 0.f);
                v2 = fmaxf(v2 + bi0, 0.f); v3 = fmaxf(v3 + bi1, 0.f);
            }
            if (EPI == 2) { v0 *= s0; v1 *= s0; v2 *= s1; v3 *= s1; }
            if (OH) {
                __half* C = (__half*)Cv;
                if (col + 1 < N) {
                    if (r0 < M) *(__half2*)(C + (size_t)r0 * ldc + col) = __floats2half2_rn(v0, v1);
                    if (r0 + 8 < M) *(__half2*)(C + (size_t)(r0 + 8) * ldc + col) = __floats2half2_rn(v2, v3);
                } else {
                    if (r0 < M) C[(size_t)r0 * ldc + col] = __float2half_rn(v0);
                    if (r0 + 8 < M) C[(size_t)(r0 + 8) * ldc + col] = __float2half_rn(v2);
                }
            } else {
                float* C = (float*)Cv;
                if (col + 1 < N) {
                    if (r0 < M) *(float2*)(C + (size_t)r0 * ldc + col) = make_float2(v0, v1);
                    if (r0 + 8 < M) *(float2*)(C + (size_t)(r0 + 8) * ldc + col) = make_float2(v2, v3);
                } else {
                    if (r0 < M) C[(size_t)r0 * ldc + col] = v0;
                    if (r0 + 8 < M) C[(size_t)(r0 + 8) * ldc + col] = v2;
                }
            }
        }
    }
}

// ---------------- small kernels -------------------------------------------
__global__ void gather_h(const int* __restrict__ p_idx, const int* __restrict__ h_idx,
                         const float* __restrict__ emb, __half* __restrict__ dst) {
    int t = blockIdx.x * blockDim.x + threadIdx.x;  // rows * (DP/8)
    if (t >= (LPn + LHn) * (DP / 8)) return;
    int r = t / (DP / 8), g = t - r * (DP / 8);
    int base = g * 8;
    int ix = (r < LPn) ? p_idx[r] : h_idx[r - LPn];
    const float* src = emb + (size_t)ix * Dn;
    __half h[8];
#pragma unroll
    for (int i = 0; i < 8; i++) {
        int c = base + i;
        h[i] = __float2half_rn((c < Dn) ? src[c] : 0.f);
    }
    *(uint4*)(dst + (size_t)r * DP + base) = *(uint4*)h;
}

__global__ void cvtpad_k(const float* __restrict__ src, __half* __restrict__ dst,
                         int rows, int sld, int dld) {
    int t = blockIdx.x * blockDim.x + threadIdx.x;
    if (t >= rows * (dld / 8)) return;
    int r = t / (dld / 8), g = t - r * (dld / 8);
    int base = g * 8;
    const float* p = src + (size_t)r * sld;
    __half h[8];
#pragma unroll
    for (int i = 0; i < 8; i++) {
        int c = base + i;
        h[i] = __float2half_rn((c < sld) ? p[c] : 0.f);
    }
    *(uint4*)(dst + (size_t)r * dld + base) = *(uint4*)h;
}

// dst[c][r] = src[r][c]; half
__global__ void transpose_h(const __half* __restrict__ src, __half* __restrict__ dst,
                            int R, int C) {
    __shared__ __half tile[32][33];
    int c = blockIdx.x * 32 + threadIdx.x;
    int r = blockIdx.y * 32 + threadIdx.y;
#pragma unroll
    for (int i = 0; i < 32; i += 8)
        if (r + i < R && c < C) tile[threadIdx.y + i][threadIdx.x] = src[(size_t)(r + i) * C + c];
    __syncthreads();
    int c2 = blockIdx.y * 32 + threadIdx.x;
    int r2 = blockIdx.x * 32 + threadIdx.y;
#pragma unroll
    for (int i = 0; i < 32; i += 8)
        if (r2 + i < C && c2 < R) dst[(size_t)(r2 + i) * R + c2] = tile[threadIdx.x][threadIdx.y + i];
}

__global__ void zero_k() {
    int t = blockIdx.x * blockDim.x + threadIdx.x;
    if (t < LHn) g_ekj[t] = 0.f;
    if (t < 2 * Hn) g_v[t] = 0.f;
}

__global__ void rowsum_k(const float* __restrict__ E, float* __restrict__ out) {
    int row = blockIdx.x * (blockDim.x / 32) + (threadIdx.x >> 5);
    int lane = threadIdx.x & 31;
    const float4* p = (const float4*)(E + (size_t)row * LHn);
    float s = 0.f;
    for (int j = lane; j < LHn / 4; j += 32) {
        float4 v = p[j];
        s += (v.x + v.y) + (v.z + v.w);
    }
#pragma unroll
    for (int o = 16; o; o >>= 1) s += __shfl_xor_sync(0xffffffffu, s, o);
    if (lane == 0) out[row] = s;
}

__global__ void colsum_acc_k(const float* __restrict__ X, float* __restrict__ out,
                             int cols, int rows_per_blk) {
    int col = blockIdx.x * blockDim.x + threadIdx.x;
    if (col >= cols) return;
    long r0 = (long)blockIdx.y * rows_per_blk;
    float s = 0.f;
    for (long r = r0; r < r0 + rows_per_blk; r++) s += X[r * cols + col];
    atomicAdd(&out[col], s);
}

__global__ void concat_h(const float* __restrict__ beta, const float* __restrict__ alpha,
                         __half* __restrict__ dst) {
    int t = blockIdx.x * blockDim.x + threadIdx.x;  // rows * (CP/8)
    if (t >= (LPn + LHn) * (CP / 8)) return;
    int r = t / (CP / 8), g = t - r * (CP / 8);
    int base = g * 8;
    const __half* e = g_embh + (size_t)r * DP;
    const float* ba = (r < LPn) ? (beta + (size_t)r * Dn) : (alpha + (size_t)(r - LPn) * Dn);
    __half h[8];
#pragma unroll
    for (int i = 0; i < 8; i++) {
        int c = base + i;
        if (c < Dn) h[i] = e[c];
        else if (c < 2 * Dn) h[i] = __float2half_rn(ba[c - Dn]);
        else h[i] = __float2half_rn(0.f);
    }
    *(uint4*)(dst + (size_t)r * CP + base) = *(uint4*)h;
}

// sum NSPL float partials -> half out
__global__ void reduce_h(const float* __restrict__ part, __half* __restrict__ out, int MN) {
    int t = blockIdx.x * blockDim.x + threadIdx.x;
    if (t >= MN / 4) return;
    float4 s = make_float4(0.f, 0.f, 0.f, 0.f);
#pragma unroll
    for (int z = 0; z < NSPL; z++) {
        float4 v = ((const float4*)(part + (size_t)z * MN))[t];
        s.x += v.x; s.y += v.y; s.z += v.z; s.w += v.w;
    }
    ((__half2*)out)[t * 2] = __floats2half2_rn(s.x, s.y);
    ((__half2*)out)[t * 2 + 1] = __floats2half2_rn(s.z, s.w);
}

__global__ void final_k(const float* __restrict__ Wg1, const float* __restrict__ bg1,
                        const float* __restrict__ Wg2, const float* __restrict__ bg2,
                        const float* __restrict__ Wg3, const float* __restrict__ bg3,
                        float* __restrict__ outv, float* __restrict__ outy) {
    __shared__ float vcat[2 * Hn];
    __shared__ float y1[Hn];
    __shared__ float y2[Hn];
    int t = threadIdx.x;  // 1024
    vcat[t] = g_v[t];
    outv[t] = g_v[t];
    __syncthreads();
    if (t < Hn) {
        float s = bg1[t];
        for (int k = 0; k < 2 * Hn; k++) s += vcat[k] * Wg1[t * 2 * Hn + k];
        y1[t] = fmaxf(s, 0.f);
    }
    __syncthreads();
    if (t < Hn) {
        float s = bg2[t];
        for (int k = 0; k < Hn; k++) s += y1[k] * Wg2[t * Hn + k];
        y2[t] = fmaxf(s, 0.f);
    }
    __syncthreads();
    if (t == 0) {
        float z[3];
        float mx = -1e30f;
        for (int c = 0; c < 3; c++) {
            float s = bg3[c];
            for (int k = 0; k < Hn; k++) s += y2[k] * Wg3[c * Hn + k];
            z[c] = s;
            mx = fmaxf(mx, z[c]);
        }
        float se = 0.f;
        for (int c = 0; c < 3; c++) { z[c] = expf(z[c] - mx); se += z[c]; }
        for (int c = 0; c < 3; c++) outy[c] = z[c] / se;
    }
}

// ---------------- launch --------------------------------------------------
#define SM_DIR (3 * (128 * 72 + 128 * 72) * 2)
#define SM_TRN (3 * (64 * 136 + 128 * 72) * 2)

extern "C" void kernel_launch(void* const* d_in, const int* in_sizes, int n_in,
                              void* d_out, int out_size) {
    const int*   p_idx = (const int*)d_in[0];
    const int*   h_idx = (const int*)d_in[1];
    const float* emb   = (const float*)d_in[2];
    const float* W_a1  = (const float*)d_in[3];
    const float* b_a1  = (const float*)d_in[4];
    const float* W_a2  = (const float*)d_in[5];
    const float* b_a2  = (const float*)d_in[6];
    const float* W_c1  = (const float*)d_in[7];
    const float* b_c1  = (const float*)d_in[8];
    const float* W_c2  = (const float*)d_in[9];
    const float* b_c2  = (const float*)d_in[10];
    const float* W_g1  = (const float*)d_in[11];
    const float* b_g1  = (const float*)d_in[12];
    const float* W_g2  = (const float*)d_in[13];
    const float* b_g2  = (const float*)d_in[14];
    const float* W_g3  = (const float*)d_in[15];
    const float* b_g3  = (const float*)d_in[16];

    float* out      = (float*)d_out;
    float* outE     = out;
    float* outBeta  = outE + (size_t)LPn * LHn;
    float* outAlpha = outBeta + (size_t)LPn * Dn;
    float* outV     = outAlpha + (size_t)LHn * Dn;
    float* outY     = outV + 2 * Hn;

    __half *embh, *embT, *t1h, *fah, *fhT, *fpT, *cath, *G1h, *G2h;
    __half *wa1, *wa2, *wc1, *wc2;
    float *part, *t2, *eik, *ekj, *v;
    cudaGetSymbolAddress((void**)&embh, g_embh);
    cudaGetSymbolAddress((void**)&embT, g_embT);
    cudaGetSymbolAddress((void**)&t1h, g_t1h);
    cudaGetSymbolAddress((void**)&fah, g_fah);
    cudaGetSymbolAddress((void**)&fhT, g_fhT);
    cudaGetSymbolAddress((void**)&fpT, g_fpT);
    cudaGetSymbolAddress((void**)&cath, g_cath);
    cudaGetSymbolAddress((void**)&G1h, g_G1h);
    cudaGetSymbolAddress((void**)&G2h, g_G2h);
    cudaGetSymbolAddress((void**)&wa1, g_wa1);
    cudaGetSymbolAddress((void**)&wa2, g_wa2);
    cudaGetSymbolAddress((void**)&wc1, g_wc1);
    cudaGetSymbolAddress((void**)&wc2, g_wc2);
    cudaGetSymbolAddress((void**)&part, g_part);
    cudaGetSymbolAddress((void**)&t2, g_t2);
    cudaGetSymbolAddress((void**)&eik, g_eik);
    cudaGetSymbolAddress((void**)&ekj, g_ekj);
    cudaGetSymbolAddress((void**)&v, g_v);

    cudaFuncSetAttribute(hgemm<false, 1, true, false>,  cudaFuncAttributeMaxDynamicSharedMemorySize, SM_DIR);
    cudaFuncSetAttribute(hgemm<false, 0, false, false>, cudaFuncAttributeMaxDynamicSharedMemorySize, SM_DIR);
    cudaFuncSetAttribute(hgemm<false, 0, false, true>,  cudaFuncAttributeMaxDynamicSharedMemorySize, SM_DIR);
    cudaFuncSetAttribute(hgemm<false, 2, false, false>, cudaFuncAttributeMaxDynamicSharedMemorySize, SM_DIR);
    cudaFuncSetAttribute(hgemm<true, 2, false, false>,  cudaFuncAttributeMaxDynamicSharedMemorySize, SM_TRN);
    cudaFuncSetAttribute(hgemm<false, 1, false, false>, cudaFuncAttributeMaxDynamicSharedMemorySize, SM_DIR);

    const int TB = 256;
    const int MT = LPn + LHn;  // 8192
    const __half* fhR = fah + (size_t)LPn * Hn;  // reshape(fh,[H,LH]) = [512][4096]

    // convert inputs to fp16 (padded), transpose emb, zero accumulators
    gather_h<<<(MT * (DP / 8) + TB - 1) / TB, TB>>>(p_idx, h_idx, emb, embh);
    cvtpad_k<<<(Hn * (DP / 8) + TB - 1) / TB, TB>>>(W_a1, wa1, Hn, Dn, DP);
    cvtpad_k<<<(Hn * (Hn / 8) + TB - 1) / TB, TB>>>(W_a2, wa2, Hn, Hn, Hn);
    cvtpad_k<<<(Hn * (CP / 8) + TB - 1) / TB, TB>>>(W_c1, wc1, Hn, 2 * Dn, CP);
    cvtpad_k<<<(Hn * (Hn / 8) + TB - 1) / TB, TB>>>(W_c2, wc2, Hn, Hn, Hn);
    transpose_h<<<dim3(DP / 32 + 1, MT / 32), dim3(32, 8)>>>(embh, embT, MT, DP);
    zero_k<<<16, 256>>>();

    // attend (merged p|h)
    hgemm<false, 1, true, false><<<dim3(Hn / 128, MT / 128), 256, SM_DIR>>>(
        embh, DP, wa1, DP, b_a1, t1h, Hn, MT, Hn, DP, 0);
    hgemm<false, 1, true, false><<<dim3(Hn / 128, MT / 128), 256, SM_DIR>>>(
        t1h, Hn, wa2, Hn, b_a2, fah, Hn, MT, Hn, Hn, 0);

    // transposes of attend outputs
    transpose_h<<<dim3(LHn / 32, Hn / 32), dim3(32, 8)>>>(fhR, fhT, Hn, LHn);  // [4096][512]
    transpose_h<<<dim3(Hn / 32, LPn / 32), dim3(32, 8)>>>(fah, fpT, LPn, Hn);  // [512][4096]

    // E = fp @ fhR : A=fah, B=fhT (W-form [4096][512]) -> fp32 out
    hgemm<false, 0, false, false><<<dim3(LHn / 128, LPn / 128), 256, SM_DIR>>>(
        fah, Hn, fhT, Hn, nullptr, outE, LHn, LPn, LHn, Hn, 0);

    rowsum_k<<<LPn / 8, 256>>>(outE, eik);
    colsum_acc_k<<<dim3(LHn / 256, 32), 256>>>(outE, ekj, LHn, LPn / 32);

    // G1T [300][512] = hembT @ fhR^T : A = embT+LPn (ld MT), B = fhR W-form [512][4096]
    hgemm<false, 0, false, true><<<dim3(4, 3, NSPL), 256, SM_DIR>>>(
        embT + LPn, MT, fhR, LHn, nullptr, part, Hn, Dn, Hn, LHn, LHn / NSPL);
    reduce_h<<<(Dn * Hn / 4 + TB - 1) / TB, TB>>>(part, G1h, Dn * Hn);

    // G2T [300][512] = pembT @ fp : A = embT (ld MT), B = fpT W-form [512][4096]
    hgemm<false, 0, false, true><<<dim3(4, 3, NSPL), 256, SM_DIR>>>(
        embT, MT, fpT, LPn, nullptr, part, Hn, Dn, Hn, LPn, LPn / NSPL);
    reduce_h<<<(Dn * Hn / 4 + TB - 1) / TB, TB>>>(part, G2h, Dn * Hn);

    // beta = diag(1/eik) * fp @ G1 : A=fah [4096][512], B=G1h [300][512]
    hgemm<false, 2, false, false><<<dim3(3, LPn / 128), 256, SM_DIR>>>(
        fah, Hn, G1h, Hn, eik, outBeta, Dn, LPn, Dn, Hn, 0);

    // alpha = diag(1/ekj) * fhR^T @ G2 : A = fhR AT-form (lda=4096), B=G2h
    hgemm<true, 2, false, false><<<dim3(3, LHn / 128), 256, SM_TRN>>>(
        fhR, LHn, G2h, Hn, ekj, outAlpha, Dn, LHn, Dn, Hn, 0);

    // comp (merged)
    concat_h<<<(MT * (CP / 8) + TB - 1) / TB, TB>>>(outBeta, outAlpha, cath);
    hgemm<false, 1, true, false><<<dim3(Hn / 128, MT / 128), 256, SM_DIR>>>(
        cath, CP, wc1, CP, b_c1, t1h, Hn, MT, Hn, CP, 0);
    hgemm<false, 1, false, false><<<dim3(Hn / 128, MT / 128), 256, SM_DIR>>>(
        t1h, Hn, wc2, Hn, b_c2, t2, Hn, MT, Hn, Hn, 0);
    colsum_acc_k<<<dim3(Hn / 256, 32), 256>>>(t2, v, Hn, LPn / 32);
    colsum_acc_k<<<dim3(Hn / 256, 32), 256>>>(t2 + (size_t)LPn * Hn, v + Hn, Hn, LHn / 32);

    final_k<<<1, 1024>>>(W_g1, b_g1, W_g2, b_g2, W_g3, b_g3, outV, outY);
}

// round 10
// speedup vs baseline: 1.4531x; 1.0147x over previous
#include <cuda_runtime.h>
#include <cuda_fp16.h>
#include <cstdint>

#define LPn 4096
#define LHn 4096
#define Dn 300
#define Hn 512
#define NSPL 8
#define DP 304   // Dn padded to x8
#define CP 608   // 2*Dn padded to x8

// ---------------- scratch (device globals; no allocation allowed) ----------
__device__ __half g_embh[(LPn + LHn) * DP];
__device__ __half g_embT[DP * (LPn + LHn)];
__device__ __half g_t1h[(LPn + LHn) * Hn];
__device__ __half g_fah[(LPn + LHn) * Hn];
__device__ __half g_fhT[LHn * Hn];
__device__ __half g_fpT[Hn * LPn];
__device__ __half g_cath[(LPn + LHn) * CP];
__device__ __half g_G1h[Dn * Hn];
__device__ __half g_G2h[Dn * Hn];
__device__ __half g_wa1[Hn * DP];
__device__ __half g_wa2[Hn * Hn];
__device__ __half g_wc1[Hn * CP];
__device__ __half g_wc2[Hn * Hn];
__device__ float g_part[NSPL * Dn * Hn];
__device__ float g_eik[LPn];
__device__ float g_ekj[LHn];
__device__ float g_v[2 * Hn];

// ---------------- helpers ---------------------------------------------------
__device__ __forceinline__ void cpa16(uint32_t saddr, const void* g, uint32_t vb) {
    asm volatile("cp.async.cg.shared.global [%0], [%1], 16, %2;"
                 ::"r"(saddr), "l"(g), "r"(vb));
}
#define CP_COMMIT() asm volatile("cp.async.commit_group;" ::: "memory")
#define CP_WAIT1() asm volatile("cp.async.wait_group 1;" ::: "memory")

__device__ __forceinline__ void mma16(float* c, const uint32_t* a, uint32_t b0, uint32_t b1) {
    asm volatile(
        "mma.sync.aligned.m16n8k16.row.col.f32.f16.f16.f32 "
        "{%0,%1,%2,%3}, {%4,%5,%6,%7}, {%8,%9}, {%0,%1,%2,%3};"
        : "+f"(c[0]), "+f"(c[1]), "+f"(c[2]), "+f"(c[3])
        : "r"(a[0]), "r"(a[1]), "r"(a[2]), "r"(a[3]), "r"(b0), "r"(b1));
}
__device__ __forceinline__ void ldm4(uint32_t* r, uint32_t addr) {
    asm volatile("ldmatrix.sync.aligned.m8n8.x4.shared.b16 {%0,%1,%2,%3}, [%4];"
                 : "=r"(r[0]), "=r"(r[1]), "=r"(r[2]), "=r"(r[3]) : "r"(addr));
}
__device__ __forceinline__ void ldm4t(uint32_t* r, uint32_t addr) {
    asm volatile("ldmatrix.sync.aligned.m8n8.x4.trans.shared.b16 {%0,%1,%2,%3}, [%4];"
                 : "=r"(r[0]), "=r"(r[1]), "=r"(r[2]), "=r"(r[3]) : "r"(addr));
}

__device__ __forceinline__ void loadDirH(const __half* __restrict__ src, int ld,
                                         int row0, int rlim, int k0, int kend,
                                         uint32_t saddr) {
    int t = threadIdx.x;
    int r = t >> 1, kb = (t & 1) * 32;
    int gr = row0 + r;
    bool rok = gr < rlim;
    const __half* p = src + (size_t)(rok ? gr : row0) * ld + k0 + kb;
    uint32_t sa = saddr + (uint32_t)(r * 72 + kb) * 2;
#pragma unroll
    for (int j = 0; j < 4; j++) {
        int gk = k0 + kb + j * 8;
        uint32_t vb = (rok && gk + 8 <= kend) ? 16u : 0u;
        cpa16(sa + j * 16, p + j * 8, vb);
    }
}

__device__ __forceinline__ void loadTransH(const __half* __restrict__ src, int ld,
                                           int c0, int clim, int k0, int kend,
                                           uint32_t saddr) {
    int t = threadIdx.x;
    int k = t >> 2;
    int gk = k0 + k;
    bool kok = gk < kend;
    const __half* p = src + (size_t)(kok ? gk : k0) * ld + c0;
    uint32_t sa = saddr + (uint32_t)(k * 136) * 2;
#pragma unroll
    for (int j = 0; j < 4; j++) {
        int moff = ((t & 3) * 4 + j) * 8;
        int gm = c0 + moff;
        uint32_t vb = (kok && gm + 8 <= clim) ? 16u : 0u;
        cpa16(sa + (uint32_t)moff * 2, p + moff, vb);
    }
}

// ---------------- fp16 mma GEMM, cp.async 3-stage, BK=64 -------------------
// EPI: 0 plain store; 1 bias+relu store; 2 rowscale store fp32 + half copy into
//      cath (ph base, col offset Dn); 3 store fp32 + atomic row sums (p1) and
//      col sums (p2); 4 bias+relu, atomic col sums into p1 (+Hn for h-rows),
//      NO store.
template <bool AT, int EPI, bool OH, bool SPLITK>
__global__ void __launch_bounds__(256, 2)
hgemm(const __half* __restrict__ A, int lda,
      const __half* __restrict__ B, int ldb,
      const float* __restrict__ aux,
      void* __restrict__ Cv, int ldc,
      int M, int N, int K, int Ksub,
      float* __restrict__ p1, float* __restrict__ p2,
      __half* __restrict__ ph) {
    constexpr int AWH = AT ? 64 * 136 : 128 * 72;
    constexpr int BWH = 128 * 72;
    constexpr int STH = AWH + BWH;
    extern __shared__ __half smh[];
    const uint32_t sbase = (uint32_t)__cvta_generic_to_shared(smh);

    const int tid = threadIdx.x, wid = tid >> 5, lane = tid & 31;
    const int gid = lane >> 2, tig = lane & 3;
    const int wm = wid >> 1, wn = wid & 1;
    const int bm = blockIdx.y * 128, bn = blockIdx.x * 128;

    int k_off = 0, Kloc = K;
    if (SPLITK) {
        k_off = blockIdx.z * Ksub;
        Kloc = Ksub;
        Cv = (void*)((float*)Cv + (size_t)blockIdx.z * M * ldc);
    }
    const int kend = k_off + Kloc;
    const int NC = (Kloc + 63) / 64;

    float acc[2][8][4];
#pragma unroll
    for (int i = 0; i < 2; i++)
#pragma unroll
        for (int j = 0; j < 8; j++)
#pragma unroll
            for (int q = 0; q < 4; q++) acc[i][j][q] = 0.f;

    uint32_t a_off;
    if (AT) {
        int krow = ((lane >> 4) << 3) + (lane & 7);
        int moff = ((lane >> 3) & 1) * 8;
        a_off = (uint32_t)(krow * 136 + wm * 32 + moff) * 2;
    } else {
        a_off = (uint32_t)((wm * 32 + (lane & 15)) * 72 + (lane >> 4) * 8) * 2;
    }
    const uint32_t b_off =
        (uint32_t)AWH * 2 +
        (uint32_t)((wn * 64 + ((lane >> 4) << 3) + (lane & 7)) * 72 + ((lane >> 3) & 1) * 8) * 2;

#pragma unroll
    for (int pc = 0; pc < 2; pc++) {
        uint32_t sA = sbase + (uint32_t)(pc * STH) * 2;
        uint32_t sB = sA + (uint32_t)AWH * 2;
        int k0 = k_off + pc * 64;
        if (AT) loadTransH(A, lda, bm, M, k0, kend, sA);
        else    loadDirH(A, lda, bm, M, k0, kend, sA);
        loadDirH(B, ldb, bn, N, k0, kend, sB);
        CP_COMMIT();
    }

    for (int kc = 0; kc < NC; kc++) {
        CP_WAIT1();
        __syncthreads();
        if (kc + 2 < NC) {
            int st = (kc + 2) % 3;
            int k0 = k_off + (kc + 2) * 64;
            uint32_t sA = sbase + (uint32_t)(st * STH) * 2;
            uint32_t sB = sA + (uint32_t)AWH * 2;
            if (AT) loadTransH(A, lda, bm, M, k0, kend, sA);
            else    loadDirH(A, lda, bm, M, k0, kend, sA);
            loadDirH(B, ldb, bn, N, k0, kend, sB);
        }
        CP_COMMIT();

        const uint32_t stoff = (uint32_t)((kc % 3) * STH) * 2;
#pragma unroll
        for (int kk = 0; kk < 4; kk++) {
            uint32_t a[2][4];
            if (AT) {
                uint32_t ab = sbase + stoff + a_off + (uint32_t)(kk * 16 * 136) * 2;
                ldm4t(a[0], ab);
                ldm4t(a[1], ab + 16 * 2);
            } else {
                uint32_t ab = sbase + stoff + a_off + (uint32_t)(kk * 16) * 2;
                ldm4(a[0], ab);
                ldm4(a[1], ab + (uint32_t)(16 * 72) * 2);
            }
            uint32_t b[8][2];
#pragma unroll
            for (int nj = 0; nj < 4; nj++) {
                uint32_t r[4];
                ldm4(r, sbase + stoff + b_off + (uint32_t)(nj * 16 * 72 + kk * 16) * 2);
                b[2 * nj][0] = r[0]; b[2 * nj][1] = r[1];
                b[2 * nj + 1][0] = r[2]; b[2 * nj + 1][1] = r[3];
            }
#pragma unroll
            for (int ni = 0; ni < 8; ni++) {
                mma16(acc[0][ni], a[0], b[ni][0], b[ni][1]);
                mma16(acc[1][ni], a[1], b[ni][0], b[ni][1]);
            }
        }
    }

    // ---------------- epilogue ----------------
    float csum0[8], csum1[8];
    if (EPI == 3 || EPI == 4) {
#pragma unroll
        for (int ni = 0; ni < 8; ni++) { csum0[ni] = 0.f; csum1[ni] = 0.f; }
    }
#pragma unroll
    for (int mi = 0; mi < 2; mi++) {
        int r0 = bm + wm * 32 + mi * 16 + gid;
        float s0 = 1.f, s1 = 1.f;
        if (EPI == 2) {
            if (r0 < M) s0 = 1.f / aux[r0];
            if (r0 + 8 < M) s1 = 1.f / aux[r0 + 8];
        }
        float rs0 = 0.f, rs1 = 0.f;
#pragma unroll
        for (int ni = 0; ni < 8; ni++) {
            int col = bn + wn * 64 + ni * 8 + tig * 2;
            if (col >= N) continue;
            float v0 = acc[mi][ni][0], v1 = acc[mi][ni][1];
            float v2 = acc[mi][ni][2], v3 = acc[mi][ni][3];
            if (EPI == 1 || EPI == 4) {
                float bi0 = aux[col];
                float bi1 = (col + 1 < N) ? aux[col + 1] : 0.f;
                v0 = fmaxf(v0 + bi0, 0.f); v1 = fmaxf(v1 + bi1, 0.f);
                v2 = fmaxf(v2 + bi0, 0.f); v3 = fmaxf(v3 + bi1, 0.f);
            }
            if (EPI == 2) { v0 *= s0; v1 *= s0; v2 *= s1; v3 *= s1; }
            if (EPI != 4) {
                if (OH) {
                    __half* C = (__half*)Cv;
                    if (col + 1 < N) {
                        if (r0 < M) *(__half2*)(C + (size_t)r0 * ldc + col) = __floats2half2_rn(v0, v1);
                        if (r0 + 8 < M) *(__half2*)(C + (size_t)(r0 + 8) * ldc + col) = __floats2half2_rn(v2, v3);
                    } else {
                        if (r0 < M) C[(size_t)r0 * ldc + col] = __float2half_rn(v0);
                        if (r0 + 8 < M) C[(size_t)(r0 + 8) * ldc + col] = __float2half_rn(v2);
                    }
                } else {
                    float* C = (float*)Cv;
                    if (col + 1 < N) {
                        if (r0 < M) *(float2*)(C + (size_t)r0 * ldc + col) = make_float2(v0, v1);
                        if (r0 + 8 < M) *(float2*)(C + (size_t)(r0 + 8) * ldc + col) = make_float2(v2, v3);
                    } else {
                        if (r0 < M) C[(size_t)r0 * ldc + col] = v0;
                        if (r0 + 8 < M) C[(size_t)(r0 + 8) * ldc + col] = v2;
                    }
                }
            }
            if (EPI == 2) {  // also write fp16 into cath at column offset Dn
                if (r0 < M) *(__half2*)(ph + (size_t)r0 * CP + Dn + col) = __floats2half2_rn(v0, v1);
                if (r0 + 8 < M) *(__half2*)(ph + (size_t)(r0 + 8) * CP + Dn + col) = __floats2half2_rn(v2, v3);
            }
            if (EPI == 3) {
                rs0 += v0 + v1; rs1 += v2 + v3;
                csum0[ni] += v0 + v2; csum1[ni] += v1 + v3;
            }
            if (EPI == 4) {
                csum0[ni] += v0 + v2; csum1[ni] += v1 + v3;
            }
        }
        if (EPI == 3) {  // row-sum partials: reduce over tig (cols), atomic to p1
            rs0 += __shfl_xor_sync(0xffffffffu, rs0, 1);
            rs0 += __shfl_xor_sync(0xffffffffu, rs0, 2);
            rs1 += __shfl_xor_sync(0xffffffffu, rs1, 1);
            rs1 += __shfl_xor_sync(0xffffffffu, rs1, 2);
            if (tig == 0) {
                atomicAdd(&p1[r0], rs0);
                atomicAdd(&p1[r0 + 8], rs1);
            }
        }
    }
    if (EPI == 3 || EPI == 4) {  // col-sum partials: reduce over gid (rows)
        float* cbase = (EPI == 3) ? p2 : (p1 + ((bm >= LPn) ? Hn : 0));
#pragma unroll
        for (int ni = 0; ni < 8; ni++) {
            int col = bn + wn * 64 + ni * 8 + tig * 2;
            if (col >= N) continue;
            float c0 = csum0[ni], c1 = csum1[ni];
            c0 += __shfl_xor_sync(0xffffffffu, c0, 4);
            c0 += __shfl_xor_sync(0xffffffffu, c0, 8);
            c0 += __shfl_xor_sync(0xffffffffu, c0, 16);
            c1 += __shfl_xor_sync(0xffffffffu, c1, 4);
            c1 += __shfl_xor_sync(0xffffffffu, c1, 8);
            c1 += __shfl_xor_sync(0xffffffffu, c1, 16);
            if (gid == 0) {
                atomicAdd(&cbase[col], c0);
                atomicAdd(&cbase[col + 1], c1);
            }
        }
    }
}

// ---------------- small kernels -------------------------------------------
__global__ void gather_h(const int* __restrict__ p_idx, const int* __restrict__ h_idx,
                         const float* __restrict__ emb, __half* __restrict__ dst) {
    int t = blockIdx.x * blockDim.x + threadIdx.x;
    if (t >= (LPn + LHn) * (DP / 8)) return;
    int r = t / (DP / 8), g = t - r * (DP / 8);
    int base = g * 8;
    int ix = (r < LPn) ? p_idx[r] : h_idx[r - LPn];
    const float* src = emb + (size_t)ix * Dn;
    __half h[8];
#pragma unroll
    for (int i = 0; i < 8; i++) {
        int c = base + i;
        h[i] = __float2half_rn((c < Dn) ? src[c] : 0.f);
    }
    *(uint4*)(dst + (size_t)r * DP + base) = *(uint4*)h;
}

__global__ void cvtpad_k(const float* __restrict__ src, __half* __restrict__ dst,
                         int rows, int sld, int dld) {
    int t = blockIdx.x * blockDim.x + threadIdx.x;
    if (t >= rows * (dld / 8)) return;
    int r = t / (dld / 8), g = t - r * (dld / 8);
    int base = g * 8;
    const float* p = src + (size_t)r * sld;
    __half h[8];
#pragma unroll
    for (int i = 0; i < 8; i++) {
        int c = base + i;
        h[i] = __float2half_rn((c < sld) ? p[c] : 0.f);
    }
    *(uint4*)(dst + (size_t)r * dld + base) = *(uint4*)h;
}

__global__ void transpose_h(const __half* __restrict__ src, __half* __restrict__ dst,
                            int R, int C) {
    __shared__ __half tile[32][33];
    int c = blockIdx.x * 32 + threadIdx.x;
    int r = blockIdx.y * 32 + threadIdx.y;
#pragma unroll
    for (int i = 0; i < 32; i += 8)
        if (r + i < R && c < C) tile[threadIdx.y + i][threadIdx.x] = src[(size_t)(r + i) * C + c];
    __syncthreads();
    int c2 = blockIdx.y * 32 + threadIdx.x;
    int r2 = blockIdx.x * 32 + threadIdx.y;
#pragma unroll
    for (int i = 0; i < 32; i += 8)
        if (r2 + i < C && c2 < R) dst[(size_t)(r2 + i) * R + c2] = tile[threadIdx.x][threadIdx.y + i];
}

__global__ void zero_k() {
    int t = blockIdx.x * blockDim.x + threadIdx.x;
    if (t < LPn) g_eik[t] = 0.f;
    if (t < LHn) g_ekj[t] = 0.f;
    if (t < 2 * Hn) g_v[t] = 0.f;
}

// prefill cath: emb columns [0,304) copied from embh (tail 300..303 is junk
// that beta/alpha later overwrite), padding [600,608) zeroed. Middle skipped.
__global__ void catfill_k(__half* __restrict__ dst) {
    int t = blockIdx.x * blockDim.x + threadIdx.x;
    if (t >= (LPn + LHn) * (CP / 8)) return;
    int r = t / (CP / 8), g = t - r * (CP / 8);
    int base = g * 8;
    if (base < DP) {
        *(uint4*)(dst + (size_t)r * CP + base) = *(const uint4*)(g_embh + (size_t)r * DP + base);
    } else if (base >= 2 * Dn) {
        uint4 z = make_uint4(0u, 0u, 0u, 0u);
        *(uint4*)(dst + (size_t)r * CP + base) = z;
    }
}

__global__ void reduce_h(const float* __restrict__ part, __half* __restrict__ out, int MN) {
    int t = blockIdx.x * blockDim.x + threadIdx.x;
    if (t >= MN / 4) return;
    float4 s = make_float4(0.f, 0.f, 0.f, 0.f);
#pragma unroll
    for (int z = 0; z < NSPL; z++) {
        float4 v = ((const float4*)(part + (size_t)z * MN))[t];
        s.x += v.x; s.y += v.y; s.z += v.z; s.w += v.w;
    }
    ((__half2*)out)[t * 2] = __floats2half2_rn(s.x, s.y);
    ((__half2*)out)[t * 2 + 1] = __floats2half2_rn(s.z, s.w);
}

__global__ void final_k(const float* __restrict__ Wg1, const float* __restrict__ bg1,
                        const float* __restrict__ Wg2, const float* __restrict__ bg2,
                        const float* __restrict__ Wg3, const float* __restrict__ bg3,
                        float* __restrict__ outv, float* __restrict__ outy) {
    __shared__ float vcat[2 * Hn];
    __shared__ float y1[Hn];
    __shared__ float y2[Hn];
    int t = threadIdx.x;  // 1024
    vcat[t] = g_v[t];
    outv[t] = g_v[t];
    __syncthreads();
    if (t < Hn) {
        float s = bg1[t];
        for (int k = 0; k < 2 * Hn; k++) s += vcat[k] * Wg1[t * 2 * Hn + k];
        y1[t] = fmaxf(s, 0.f);
    }
    __syncthreads();
    if (t < Hn) {
        float s = bg2[t];
        for (int k = 0; k < Hn; k++) s += y1[k] * Wg2[t * Hn + k];
        y2[t] = fmaxf(s, 0.f);
    }
    __syncthreads();
    if (t == 0) {
        float z[3];
        float mx = -1e30f;
        for (int c = 0; c < 3; c++) {
            float s = bg3[c];
            for (int k = 0; k < Hn; k++) s += y2[k] * Wg3[c * Hn + k];
            z[c] = s;
            mx = fmaxf(mx, z[c]);
        }
        float se = 0.f;
        for (int c = 0; c < 3; c++) { z[c] = expf(z[c] - mx); se += z[c]; }
        for (int c = 0; c < 3; c++) outy[c] = z[c] / se;
    }
}

// ---------------- launch --------------------------------------------------
#define SM_DIR (3 * (128 * 72 + 128 * 72) * 2)
#define SM_TRN (3 * (64 * 136 + 128 * 72) * 2)

extern "C" void kernel_launch(void* const* d_in, const int* in_sizes, int n_in,
                              void* d_out, int out_size) {
    const int*   p_idx = (const int*)d_in[0];
    const int*   h_idx = (const int*)d_in[1];
    const float* emb   = (const float*)d_in[2];
    const float* W_a1  = (const float*)d_in[3];
    const float* b_a1  = (const float*)d_in[4];
    const float* W_a2  = (const float*)d_in[5];
    const float* b_a2  = (const float*)d_in[6];
    const float* W_c1  = (const float*)d_in[7];
    const float* b_c1  = (const float*)d_in[8];
    const float* W_c2  = (const float*)d_in[9];
    const float* b_c2  = (const float*)d_in[10];
    const float* W_g1  = (const float*)d_in[11];
    const float* b_g1  = (const float*)d_in[12];
    const float* W_g2  = (const float*)d_in[13];
    const float* b_g2  = (const float*)d_in[14];
    const float* W_g3  = (const float*)d_in[15];
    const float* b_g3  = (const float*)d_in[16];

    float* out      = (float*)d_out;
    float* outE     = out;
    float* outBeta  = outE + (size_t)LPn * LHn;
    float* outAlpha = outBeta + (size_t)LPn * Dn;
    float* outV     = outAlpha + (size_t)LHn * Dn;
    float* outY     = outV + 2 * Hn;

    __half *embh, *embT, *t1h, *fah, *fhT, *fpT, *cath, *G1h, *G2h;
    __half *wa1, *wa2, *wc1, *wc2;
    float *part, *eik, *ekj, *v;
    cudaGetSymbolAddress((void**)&embh, g_embh);
    cudaGetSymbolAddress((void**)&embT, g_embT);
    cudaGetSymbolAddress((void**)&t1h, g_t1h);
    cudaGetSymbolAddress((void**)&fah, g_fah);
    cudaGetSymbolAddress((void**)&fhT, g_fhT);
    cudaGetSymbolAddress((void**)&fpT, g_fpT);
    cudaGetSymbolAddress((void**)&cath, g_cath);
    cudaGetSymbolAddress((void**)&G1h, g_G1h);
    cudaGetSymbolAddress((void**)&G2h, g_G2h);
    cudaGetSymbolAddress((void**)&wa1, g_wa1);
    cudaGetSymbolAddress((void**)&wa2, g_wa2);
    cudaGetSymbolAddress((void**)&wc1, g_wc1);
    cudaGetSymbolAddress((void**)&wc2, g_wc2);
    cudaGetSymbolAddress((void**)&part, g_part);
    cudaGetSymbolAddress((void**)&eik, g_eik);
    cudaGetSymbolAddress((void**)&ekj, g_ekj);
    cudaGetSymbolAddress((void**)&v, g_v);

    cudaFuncSetAttribute(hgemm<false, 1, true, false>,  cudaFuncAttributeMaxDynamicSharedMemorySize, SM_DIR);
    cudaFuncSetAttribute(hgemm<false, 0, false, true>,  cudaFuncAttributeMaxDynamicSharedMemorySize, SM_DIR);
    cudaFuncSetAttribute(hgemm<false, 3, false, false>, cudaFuncAttributeMaxDynamicSharedMemorySize, SM_DIR);
    cudaFuncSetAttribute(hgemm<false, 2, false, false>, cudaFuncAttributeMaxDynamicSharedMemorySize, SM_DIR);
    cudaFuncSetAttribute(hgemm<true, 2, false, false>,  cudaFuncAttributeMaxDynamicSharedMemorySize, SM_TRN);
    cudaFuncSetAttribute(hgemm<false, 4, false, false>, cudaFuncAttributeMaxDynamicSharedMemorySize, SM_DIR);

    const int TB = 256;
    const int MT = LPn + LHn;  // 8192
    const __half* fhR = fah + (size_t)LPn * Hn;  // reshape(fh,[H,LH]) = [512][4096]

    // prep: gather, weight conversion, emb transpose, zeroing, cat prefill
    gather_h<<<(MT * (DP / 8) + TB - 1) / TB, TB>>>(p_idx, h_idx, emb, embh);
    cvtpad_k<<<(Hn * (DP / 8) + TB - 1) / TB, TB>>>(W_a1, wa1, Hn, Dn, DP);
    cvtpad_k<<<(Hn * (Hn / 8) + TB - 1) / TB, TB>>>(W_a2, wa2, Hn, Hn, Hn);
    cvtpad_k<<<(Hn * (CP / 8) + TB - 1) / TB, TB>>>(W_c1, wc1, Hn, 2 * Dn, CP);
    cvtpad_k<<<(Hn * (Hn / 8) + TB - 1) / TB, TB>>>(W_c2, wc2, Hn, Hn, Hn);
    transpose_h<<<dim3(DP / 32 + 1, MT / 32), dim3(32, 8)>>>(embh, embT, MT, DP);
    zero_k<<<16, 256>>>();
    catfill_k<<<(MT * (CP / 8) + TB - 1) / TB, TB>>>(cath);

    // attend (merged p|h)
    hgemm<false, 1, true, false><<<dim3(Hn / 128, MT / 128), 256, SM_DIR>>>(
        embh, DP, wa1, DP, b_a1, t1h, Hn, MT, Hn, DP, 0, nullptr, nullptr, nullptr);
    hgemm<false, 1, true, false><<<dim3(Hn / 128, MT / 128), 256, SM_DIR>>>(
        t1h, Hn, wa2, Hn, b_a2, fah, Hn, MT, Hn, Hn, 0, nullptr, nullptr, nullptr);

    // transposes of attend outputs
    transpose_h<<<dim3(LHn / 32, Hn / 32), dim3(32, 8)>>>(fhR, fhT, Hn, LHn);
    transpose_h<<<dim3(Hn / 32, LPn / 32), dim3(32, 8)>>>(fah, fpT, LPn, Hn);

    // G1T [300][512] = hembT @ fhR^T ; G2T = pembT @ fp (split-K)
    hgemm<false, 0, false, true><<<dim3(4, 3, NSPL), 256, SM_DIR>>>(
        embT + LPn, MT, fhR, LHn, nullptr, part, Hn, Dn, Hn, LHn, LHn / NSPL,
        nullptr, nullptr, nullptr);
    reduce_h<<<(Dn * Hn / 4 + TB - 1) / TB, TB>>>(part, G1h, Dn * Hn);
    hgemm<false, 0, false, true><<<dim3(4, 3, NSPL), 256, SM_DIR>>>(
        embT, MT, fpT, LPn, nullptr, part, Hn, Dn, Hn, LPn, LPn / NSPL,
        nullptr, nullptr, nullptr);
    reduce_h<<<(Dn * Hn / 4 + TB - 1) / TB, TB>>>(part, G2h, Dn * Hn);

    // E = fp @ fhR with fused row/col sums (eik, ekj via atomics)
    hgemm<false, 3, false, false><<<dim3(LHn / 128, LPn / 128), 256, SM_DIR>>>(
        fah, Hn, fhT, Hn, nullptr, outE, LHn, LPn, LHn, Hn, 0, eik, ekj, nullptr);

    // beta = diag(1/eik) * fp @ G1 -> outBeta fp32 + cath halves (rows 0..LPn)
    hgemm<false, 2, false, false><<<dim3(3, LPn / 128), 256, SM_DIR>>>(
        fah, Hn, G1h, Hn, eik, outBeta, Dn, LPn, Dn, Hn, 0, nullptr, nullptr, cath);

    // alpha = diag(1/ekj) * fhR^T @ G2 -> outAlpha fp32 + cath halves (rows LPn..)
    hgemm<true, 2, false, false><<<dim3(3, LHn / 128), 256, SM_TRN>>>(
        fhR, LHn, G2h, Hn, ekj, outAlpha, Dn, LHn, Dn, Hn, 0,
        nullptr, nullptr, cath + (size_t)LPn * CP);

    // comp: cath -> t1h -> fused column sums into v (no t2 buffer)
    hgemm<false, 1, true, false><<<dim3(Hn / 128, MT / 128), 256, SM_DIR>>>(
        cath, CP, wc1, CP, b_c1, t1h, Hn, MT, Hn, CP, 0, nullptr, nullptr, nullptr);
    hgemm<false, 4, false, false><<<dim3(Hn / 128, MT / 128), 256, SM_DIR>>>(
        t1h, Hn, wc2, Hn, b_c2, nullptr, Hn, MT, Hn, Hn, 0, v, nullptr, nullptr);

    final_k<<<1, 1024>>>(W_g1, b_g1, W_g2, b_g2, W_g3, b_g3, outV, outY);
}

// round 12
// speedup vs baseline: 1.5237x; 1.0486x over previous
#include <cuda_runtime.h>
#include <cuda_fp16.h>
#include <cstdint>

#define LPn 4096
#define LHn 4096
#define Dn 300
#define Hn 512
#define NSPL 8
#define DP 304   // Dn padded to x8
#define CP 608   // 2*Dn padded to x8

// ---------------- scratch (device globals; no allocation allowed) ----------
__device__ __half g_embh[(LPn + LHn) * DP];
__device__ __half g_t1h[(LPn + LHn) * Hn];
__device__ __half g_fah[(LPn + LHn) * Hn];
__device__ __half g_cath[(LPn + LHn) * CP];
__device__ __half g_G1h[Dn * Hn];
__device__ __half g_G2h[Dn * Hn];
__device__ __half g_wa1[Hn * DP];
__device__ __half g_wa2[Hn * Hn];
__device__ __half g_wc1[Hn * CP];
__device__ __half g_wc2[Hn * Hn];
__device__ float g_part[NSPL * Dn * Hn];
__device__ float g_eik[LPn];
__device__ float g_ekj[LHn];
__device__ float g_v[2 * Hn];

// ---------------- helpers ---------------------------------------------------
__device__ __forceinline__ void cpa16(uint32_t saddr, const void* g, uint32_t vb) {
    asm volatile("cp.async.cg.shared.global [%0], [%1], 16, %2;"
                 ::"r"(saddr), "l"(g), "r"(vb));
}
#define CP_COMMIT() asm volatile("cp.async.commit_group;" ::: "memory")
#define CP_WAIT1() asm volatile("cp.async.wait_group 1;" ::: "memory")

__device__ __forceinline__ void mma16(float* c, const uint32_t* a, uint32_t b0, uint32_t b1) {
    asm volatile(
        "mma.sync.aligned.m16n8k16.row.col.f32.f16.f16.f32 "
        "{%0,%1,%2,%3}, {%4,%5,%6,%7}, {%8,%9}, {%0,%1,%2,%3};"
        : "+f"(c[0]), "+f"(c[1]), "+f"(c[2]), "+f"(c[3])
        : "r"(a[0]), "r"(a[1]), "r"(a[2]), "r"(a[3]), "r"(b0), "r"(b1));
}
__device__ __forceinline__ void ldm4(uint32_t* r, uint32_t addr) {
    asm volatile("ldmatrix.sync.aligned.m8n8.x4.shared.b16 {%0,%1,%2,%3}, [%4];"
                 : "=r"(r[0]), "=r"(r[1]), "=r"(r[2]), "=r"(r[3]) : "r"(addr));
}
__device__ __forceinline__ void ldm4t(uint32_t* r, uint32_t addr) {
    asm volatile("ldmatrix.sync.aligned.m8n8.x4.trans.shared.b16 {%0,%1,%2,%3}, [%4];"
                 : "=r"(r[0]), "=r"(r[1]), "=r"(r[2]), "=r"(r[3]) : "r"(addr));
}

// direct: src half [rows][ld]; chunk [k0,k0+64) -> smem [r][k] stride 72 halves
__device__ __forceinline__ void loadDirH(const __half* __restrict__ src, int ld,
                                         int row0, int rlim, int k0, int kend,
                                         uint32_t saddr) {
    int t = threadIdx.x;
    int r = t >> 1, kb = (t & 1) * 32;
    int gr = row0 + r;
    bool rok = gr < rlim;
    const __half* p = src + (size_t)(rok ? gr : row0) * ld + k0 + kb;
    uint32_t sa = saddr + (uint32_t)(r * 72 + kb) * 2;
#pragma unroll
    for (int j = 0; j < 4; j++) {
        int gk = k0 + kb + j * 8;
        uint32_t vb = (rok && gk + 8 <= kend) ? 16u : 0u;
        cpa16(sa + j * 16, p + j * 8, vb);
    }
}

// trans: src half [Ktot][ld]; k rows [k0,k0+64), cols [c0,c0+128) -> smem [k][c] stride 136
__device__ __forceinline__ void loadTransH(const __half* __restrict__ src, int ld,
                                           int c0, int clim, int k0, int kend,
                                           uint32_t saddr) {
    int t = threadIdx.x;
    int k = t >> 2;
    int gk = k0 + k;
    bool kok = gk < kend;
    const __half* p = src + (size_t)(kok ? gk : k0) * ld + c0;
    uint32_t sa = saddr + (uint32_t)(k * 136) * 2;
#pragma unroll
    for (int j = 0; j < 4; j++) {
        int moff = ((t & 3) * 4 + j) * 8;
        int gm = c0 + moff;
        uint32_t vb = (kok && gm + 8 <= clim) ? 16u : 0u;
        cpa16(sa + (uint32_t)moff * 2, p + moff, vb);
    }
}

// ---------------- fp16 mma GEMM, cp.async 3-stage, BK=64 -------------------
// AT: A[m,k]=src[k*lda+m] (trans-A). BT: B[k,n]=src[k*ldb+n] (trans-B);
//     else B = W-form [N,K] row-major.
// EPI: 0 plain; 1 bias+relu; 2 rowscale fp32 store + half copy into ph (+Dn);
//      3 store + atomic row sums p1 / col sums p2; 4 bias+relu, atomic col
//      sums into p1 (+Hn for h-rows), no store.
template <bool AT, bool BT, int EPI, bool OH, bool SPLITK>
__global__ void __launch_bounds__(256, 2)
hgemm(const __half* __restrict__ A, int lda,
      const __half* __restrict__ B, int ldb,
      const float* __restrict__ aux,
      void* __restrict__ Cv, int ldc,
      int M, int N, int K, int Ksub, int aclim,
      float* __restrict__ p1, float* __restrict__ p2,
      __half* __restrict__ ph) {
    constexpr int AWH = AT ? 64 * 136 : 128 * 72;
    constexpr int BWH = BT ? 64 * 136 : 128 * 72;
    constexpr int STH = AWH + BWH;
    extern __shared__ __half smh[];
    const uint32_t sbase = (uint32_t)__cvta_generic_to_shared(smh);

    const int tid = threadIdx.x, wid = tid >> 5, lane = tid & 31;
    const int gid = lane >> 2, tig = lane & 3;
    const int wm = wid >> 1, wn = wid & 1;
    const int bm = blockIdx.y * 128, bn = blockIdx.x * 128;

    int k_off = 0, Kloc = K;
    if (SPLITK) {
        k_off = blockIdx.z * Ksub;
        Kloc = Ksub;
        Cv = (void*)((float*)Cv + (size_t)blockIdx.z * M * ldc);
    }
    const int kend = k_off + Kloc;
    const int NC = (Kloc + 63) / 64;

    float acc[2][8][4];
#pragma unroll
    for (int i = 0; i < 2; i++)
#pragma unroll
        for (int j = 0; j < 8; j++)
#pragma unroll
            for (int q = 0; q < 4; q++) acc[i][j][q] = 0.f;

    uint32_t a_off;
    if (AT) {
        int krow = ((lane >> 4) << 3) + (lane & 7);
        int moff = ((lane >> 3) & 1) * 8;
        a_off = (uint32_t)(krow * 136 + wm * 32 + moff) * 2;
    } else {
        a_off = (uint32_t)((wm * 32 + (lane & 15)) * 72 + (lane >> 4) * 8) * 2;
    }
    uint32_t b_off;
    if (BT) {
        int krow = ((lane >> 3) & 1) * 8 + (lane & 7);
        int noff = (lane >> 4) * 8;
        b_off = (uint32_t)AWH * 2 + (uint32_t)(krow * 136 + wn * 64 + noff) * 2;
    } else {
        b_off = (uint32_t)AWH * 2 +
                (uint32_t)((wn * 64 + ((lane >> 4) << 3) + (lane & 7)) * 72 +
                           ((lane >> 3) & 1) * 8) * 2;
    }

#pragma unroll
    for (int pc = 0; pc < 2; pc++) {
        uint32_t sA = sbase + (uint32_t)(pc * STH) * 2;
        uint32_t sB = sA + (uint32_t)AWH * 2;
        int k0 = k_off + pc * 64;
        if (AT) loadTransH(A, lda, bm, aclim, k0, kend, sA);
        else    loadDirH(A, lda, bm, M, k0, kend, sA);
        if (BT) loadTransH(B, ldb, bn, N, k0, kend, sB);
        else    loadDirH(B, ldb, bn, N, k0, kend, sB);
        CP_COMMIT();
    }

    for (int kc = 0; kc < NC; kc++) {
        CP_WAIT1();
        __syncthreads();
        if (kc + 2 < NC) {
            int st = (kc + 2) % 3;
            int k0 = k_off + (kc + 2) * 64;
            uint32_t sA = sbase + (uint32_t)(st * STH) * 2;
            uint32_t sB = sA + (uint32_t)AWH * 2;
            if (AT) loadTransH(A, lda, bm, aclim, k0, kend, sA);
            else    loadDirH(A, lda, bm, M, k0, kend, sA);
            if (BT) loadTransH(B, ldb, bn, N, k0, kend, sB);
            else    loadDirH(B, ldb, bn, N, k0, kend, sB);
        }
        CP_COMMIT();

        const uint32_t stoff = (uint32_t)((kc % 3) * STH) * 2;
#pragma unroll
        for (int kk = 0; kk < 4; kk++) {
            uint32_t a[2][4];
            if (AT) {
                uint32_t ab = sbase + stoff + a_off + (uint32_t)(kk * 16 * 136) * 2;
                ldm4t(a[0], ab);
                ldm4t(a[1], ab + 16 * 2);
            } else {
                uint32_t ab = sbase + stoff + a_off + (uint32_t)(kk * 16) * 2;
                ldm4(a[0], ab);
                ldm4(a[1], ab + (uint32_t)(16 * 72) * 2);
            }
            uint32_t b[8][2];
#pragma unroll
            for (int nj = 0; nj < 4; nj++) {
                uint32_t r[4];
                if (BT) ldm4t(r, sbase + stoff + b_off + (uint32_t)(kk * 16 * 136 + nj * 16) * 2);
                else    ldm4 (r, sbase + stoff + b_off + (uint32_t)(nj * 16 * 72 + kk * 16) * 2);
                b[2 * nj][0] = r[0]; b[2 * nj][1] = r[1];
                b[2 * nj + 1][0] = r[2]; b[2 * nj + 1][1] = r[3];
            }
#pragma unroll
            for (int ni = 0; ni < 8; ni++) {
                mma16(acc[0][ni], a[0], b[ni][0], b[ni][1]);
                mma16(acc[1][ni], a[1], b[ni][0], b[ni][1]);
            }
        }
    }

    // ---------------- epilogue ----------------
    float csum0[8], csum1[8];
    if (EPI == 3 || EPI == 4) {
#pragma unroll
        for (int ni = 0; ni < 8; ni++) { csum0[ni] = 0.f; csum1[ni] = 0.f; }
    }
#pragma unroll
    for (int mi = 0; mi < 2; mi++) {
        int r0 = bm + wm * 32 + mi * 16 + gid;
        float s0 = 1.f, s1 = 1.f;
        if (EPI == 2) {
            if (r0 < M) s0 = 1.f / aux[r0];
            if (r0 + 8 < M) s1 = 1.f / aux[r0 + 8];
        }
        float rs0 = 0.f, rs1 = 0.f;
#pragma unroll
        for (int ni = 0; ni < 8; ni++) {
            int col = bn + wn * 64 + ni * 8 + tig * 2;
            if (col >= N) continue;
            float v0 = acc[mi][ni][0], v1 = acc[mi][ni][1];
            float v2 = acc[mi][ni][2], v3 = acc[mi][ni][3];
            if (EPI == 1 || EPI == 4) {
                float bi0 = aux[col];
                float bi1 = (col + 1 < N) ? aux[col + 1] : 0.f;
                v0 = fmaxf(v0 + bi0, 0.f); v1 = fmaxf(v1 + bi1, 0.f);
                v2 = fmaxf(v2 + bi0, 0.f); v3 = fmaxf(v3 + bi1, 0.f);
            }
            if (EPI == 2) { v0 *= s0; v1 *= s0; v2 *= s1; v3 *= s1; }
            if (EPI != 4) {
                if (OH) {
                    __half* C = (__half*)Cv;
                    if (col + 1 < N) {
                        if (r0 < M) *(__half2*)(C + (size_t)r0 * ldc + col) = __floats2half2_rn(v0, v1);
                        if (r0 + 8 < M) *(__half2*)(C + (size_t)(r0 + 8) * ldc + col) = __floats2half2_rn(v2, v3);
                    } else {
                        if (r0 < M) C[(size_t)r0 * ldc + col] = __float2half_rn(v0);
                        if (r0 + 8 < M) C[(size_t)(r0 + 8) * ldc + col] = __float2half_rn(v2);
                    }
                } else {
                    float* C = (float*)Cv;
                    if (col + 1 < N) {
                        if (r0 < M) *(float2*)(C + (size_t)r0 * ldc + col) = make_float2(v0, v1);
                        if (r0 + 8 < M) *(float2*)(C + (size_t)(r0 + 8) * ldc + col) = make_float2(v2, v3);
                    } else {
                        if (r0 < M) C[(size_t)r0 * ldc + col] = v0;
                        if (r0 + 8 < M) C[(size_t)(r0 + 8) * ldc + col] = v2;
                    }
                }
            }
            if (EPI == 2) {
                if (r0 < M) *(__half2*)(ph + (size_t)r0 * CP + Dn + col) = __floats2half2_rn(v0, v1);
                if (r0 + 8 < M) *(__half2*)(ph + (size_t)(r0 + 8) * CP + Dn + col) = __floats2half2_rn(v2, v3);
            }
            if (EPI == 3) {
                rs0 += v0 + v1; rs1 += v2 + v3;
                csum0[ni] += v0 + v2; csum1[ni] += v1 + v3;
            }
            if (EPI == 4) {
                csum0[ni] += v0 + v2; csum1[ni] += v1 + v3;
            }
        }
        if (EPI == 3) {
            rs0 += __shfl_xor_sync(0xffffffffu, rs0, 1);
            rs0 += __shfl_xor_sync(0xffffffffu, rs0, 2);
            rs1 += __shfl_xor_sync(0xffffffffu, rs1, 1);
            rs1 += __shfl_xor_sync(0xffffffffu, rs1, 2);
            if (tig == 0) {
                atomicAdd(&p1[r0], rs0);
                atomicAdd(&p1[r0 + 8], rs1);
            }
        }
    }
    if (EPI == 3 || EPI == 4) {
        float* cbase = (EPI == 3) ? p2 : (p1 + ((bm >= LPn) ? Hn : 0));
#pragma unroll
        for (int ni = 0; ni < 8; ni++) {
            int col = bn + wn * 64 + ni * 8 + tig * 2;
            if (col >= N) continue;
            float c0 = csum0[ni], c1 = csum1[ni];
            c0 += __shfl_xor_sync(0xffffffffu, c0, 4);
            c0 += __shfl_xor_sync(0xffffffffu, c0, 8);
            c0 += __shfl_xor_sync(0xffffffffu, c0, 16);
            c1 += __shfl_xor_sync(0xffffffffu, c1, 4);
            c1 += __shfl_xor_sync(0xffffffffu, c1, 8);
            c1 += __shfl_xor_sync(0xffffffffu, c1, 16);
            if (gid == 0) {
                atomicAdd(&cbase[col], c0);
                atomicAdd(&cbase[col + 1], c1);
            }
        }
    }
}

// ---------------- merged prep kernel ---------------------------------------
// sections by blockIdx.x:
//  [0,1216): gather -> embh + cath emb cols + cath tail zero
//  [1216,1292): wa1   [1292,1420): wa2   [1420,1572): wc1   [1572,1700): wc2
//  [1700,1716): zero eik/ekj/v
__device__ __forceinline__ void cvt8(const float* p, int sld_valid, __half* dst) {
    __half h[8];
#pragma unroll
    for (int i = 0; i < 8; i++) h[i] = __float2half_rn((i < sld_valid) ? p[i] : 0.f);
    *(uint4*)dst = *(uint4*)h;
}

__global__ void prep_k(const int* __restrict__ p_idx, const int* __restrict__ h_idx,
                       const float* __restrict__ emb,
                       const float* __restrict__ W_a1, const float* __restrict__ W_a2,
                       const float* __restrict__ W_c1, const float* __restrict__ W_c2) {
    int b = blockIdx.x, tid = threadIdx.x;
    if (b < 1216) {  // gather: 8192 rows * 38 groups
        int t = b * 256 + tid;
        int r = t / (DP / 8), g = t - r * (DP / 8);
        int base = g * 8;
        int ix = (r < LPn) ? p_idx[r] : h_idx[r - LPn];
        const float* src = emb + (size_t)ix * Dn;
        __half h[8];
#pragma unroll
        for (int i = 0; i < 8; i++) {
            int c = base + i;
            h[i] = __float2half_rn((c < Dn) ? src[c] : 0.f);
        }
        *(uint4*)(g_embh + (size_t)r * DP + base) = *(uint4*)h;
        *(uint4*)(g_cath + (size_t)r * CP + base) = *(uint4*)h;
        if (g == 0) {
            uint4 z = make_uint4(0u, 0u, 0u, 0u);
            *(uint4*)(g_cath + (size_t)r * CP + 2 * Dn) = z;
        }
    } else if (b < 1292) {  // wa1: [Hn][Dn] -> [Hn][DP]
        int t = (b - 1216) * 256 + tid;
        int r = t / (DP / 8), g = t - r * (DP / 8);
        int base = g * 8;
        cvt8(W_a1 + (size_t)r * Dn + base, Dn - base, g_wa1 + (size_t)r * DP + base);
    } else if (b < 1420) {  // wa2: [Hn][Hn]
        int t = (b - 1292) * 256 + tid;
        int base = (t % (Hn / 8)) * 8, r = t / (Hn / 8);
        cvt8(W_a2 + (size_t)r * Hn + base, 8, g_wa2 + (size_t)r * Hn + base);
    } else if (b < 1572) {  // wc1: [Hn][2Dn] -> [Hn][CP]
        int t = (b - 1420) * 256 + tid;
        int r = t / (CP / 8), g = t - r * (CP / 8);
        int base = g * 8;
        cvt8(W_c1 + (size_t)r * 2 * Dn + base, 2 * Dn - base, g_wc1 + (size_t)r * CP + base);
    } else if (b < 1700) {  // wc2: [Hn][Hn]
        int t = (b - 1572) * 256 + tid;
        int base = (t % (Hn / 8)) * 8, r = t / (Hn / 8);
        cvt8(W_c2 + (size_t)r * Hn + base, 8, g_wc2 + (size_t)r * Hn + base);
    } else {  // zero
        int t = (b - 1700) * 256 + tid;
        g_eik[t] = 0.f;
        g_ekj[t] = 0.f;
        if (t < 2 * Hn) g_v[t] = 0.f;
    }
}

__global__ void reduce_h(const float* __restrict__ part, __half* __restrict__ out, int MN) {
    int t = blockIdx.x * blockDim.x + threadIdx.x;
    if (t >= MN / 4) return;
    float4 s = make_float4(0.f, 0.f, 0.f, 0.f);
#pragma unroll
    for (int z = 0; z < NSPL; z++) {
        float4 v = ((const float4*)(part + (size_t)z * MN))[t];
        s.x += v.x; s.y += v.y; s.z += v.z; s.w += v.w;
    }
    ((__half2*)out)[t * 2] = __floats2half2_rn(s.x, s.y);
    ((__half2*)out)[t * 2 + 1] = __floats2half2_rn(s.z, s.w);
}

__global__ void final_k(const float* __restrict__ Wg1, const float* __restrict__ bg1,
                        const float* __restrict__ Wg2, const float* __restrict__ bg2,
                        const float* __restrict__ Wg3, const float* __restrict__ bg3,
                        float* __restrict__ outv, float* __restrict__ outy) {
    __shared__ float vcat[2 * Hn];
    __shared__ float y1[Hn];
    __shared__ float y2[Hn];
    int t = threadIdx.x;  // 1024
    vcat[t] = g_v[t];
    outv[t] = g_v[t];
    __syncthreads();
    if (t < Hn) {
        float s = bg1[t];
        for (int k = 0; k < 2 * Hn; k++) s += vcat[k] * Wg1[t * 2 * Hn + k];
        y1[t] = fmaxf(s, 0.f);
    }
    __syncthreads();
    if (t < Hn) {
        float s = bg2[t];
        for (int k = 0; k < Hn; k++) s += y1[k] * Wg2[t * Hn + k];
        y2[t] = fmaxf(s, 0.f);
    }
    __syncthreads();
    if (t == 0) {
        float z[3];
        float mx = -1e30f;
        for (int c = 0; c < 3; c++) {
            float s = bg3[c];
            for (int k = 0; k < Hn; k++) s += y2[k] * Wg3[c * Hn + k];
            z[c] = s;
            mx = fmaxf(mx, z[c]);
        }
        float se = 0.f;
        for (int c = 0; c < 3; c++) { z[c] = expf(z[c] - mx); se += z[c]; }
        for (int c = 0; c < 3; c++) outy[c] = z[c] / se;
    }
}

// ---------------- launch --------------------------------------------------
#define SM_DD (3 * (128 * 72 + 128 * 72) * 2)
#define SM_TD (3 * (64 * 136 + 128 * 72) * 2)
#define SM_DT (3 * (128 * 72 + 64 * 136) * 2)
#define SM_TT (3 * (64 * 136 + 64 * 136) * 2)

extern "C" void kernel_launch(void* const* d_in, const int* in_sizes, int n_in,
                              void* d_out, int out_size) {
    const int*   p_idx = (const int*)d_in[0];
    const int*   h_idx = (const int*)d_in[1];
    const float* emb   = (const float*)d_in[2];
    const float* W_a1  = (const float*)d_in[3];
    const float* b_a1  = (const float*)d_in[4];
    const float* W_a2  = (const float*)d_in[5];
    const float* b_a2  = (const float*)d_in[6];
    const float* W_c1  = (const float*)d_in[7];
    const float* b_c1  = (const float*)d_in[8];
    const float* W_c2  = (const float*)d_in[9];
    const float* b_c2  = (const float*)d_in[10];
    const float* W_g1  = (const float*)d_in[11];
    const float* b_g1  = (const float*)d_in[12];
    const float* W_g2  = (const float*)d_in[13];
    const float* b_g2  = (const float*)d_in[14];
    const float* W_g3  = (const float*)d_in[15];
    const float* b_g3  = (const float*)d_in[16];

    float* out      = (float*)d_out;
    float* outE     = out;
    float* outBeta  = outE + (size_t)LPn * LHn;
    float* outAlpha = outBeta + (size_t)LPn * Dn;
    float* outV     = outAlpha + (size_t)LHn * Dn;
    float* outY     = outV + 2 * Hn;

    __half *embh, *t1h, *fah, *cath, *G1h, *G2h;
    __half *wa1, *wa2, *wc1, *wc2;
    float *part, *eik, *ekj, *v;
    cudaGetSymbolAddress((void**)&embh, g_embh);
    cudaGetSymbolAddress((void**)&t1h, g_t1h);
    cudaGetSymbolAddress((void**)&fah, g_fah);
    cudaGetSymbolAddress((void**)&cath, g_cath);
    cudaGetSymbolAddress((void**)&G1h, g_G1h);
    cudaGetSymbolAddress((void**)&G2h, g_G2h);
    cudaGetSymbolAddress((void**)&wa1, g_wa1);
    cudaGetSymbolAddress((void**)&wa2, g_wa2);
    cudaGetSymbolAddress((void**)&wc1, g_wc1);
    cudaGetSymbolAddress((void**)&wc2, g_wc2);
    cudaGetSymbolAddress((void**)&part, g_part);
    cudaGetSymbolAddress((void**)&eik, g_eik);
    cudaGetSymbolAddress((void**)&ekj, g_ekj);
    cudaGetSymbolAddress((void**)&v, g_v);

    cudaFuncSetAttribute(hgemm<false, false, 1, true, false>,  cudaFuncAttributeMaxDynamicSharedMemorySize, SM_DD);
    cudaFuncSetAttribute(hgemm<true, false, 0, false, true>,   cudaFuncAttributeMaxDynamicSharedMemorySize, SM_TD);
    cudaFuncSetAttribute(hgemm<true, true, 0, false, true>,    cudaFuncAttributeMaxDynamicSharedMemorySize, SM_TT);
    cudaFuncSetAttribute(hgemm<false, true, 3, false, false>,  cudaFuncAttributeMaxDynamicSharedMemorySize, SM_DT);
    cudaFuncSetAttribute(hgemm<false, false, 2, false, false>, cudaFuncAttributeMaxDynamicSharedMemorySize, SM_DD);
    cudaFuncSetAttribute(hgemm<true, false, 2, false, false>,  cudaFuncAttributeMaxDynamicSharedMemorySize, SM_TD);
    cudaFuncSetAttribute(hgemm<false, false, 4, false, false>, cudaFuncAttributeMaxDynamicSharedMemorySize, SM_DD);

    const int TB = 256;
    const int MT = LPn + LHn;  // 8192
    const __half* fhR = fah + (size_t)LPn * Hn;  // reshape(fh,[H,LH]) = [512][4096]

    // (1) merged prep: gather + cath emb cols + weight converts + zeroing
    prep_k<<<1716, TB>>>(p_idx, h_idx, emb, W_a1, W_a2, W_c1, W_c2);

    // (2,3) attend (merged p|h)
    hgemm<false, false, 1, true, false><<<dim3(Hn / 128, MT / 128), 256, SM_DD>>>(
        embh, DP, wa1, DP, b_a1, t1h, Hn, MT, Hn, DP, 0, 0, nullptr, nullptr, nullptr);
    hgemm<false, false, 1, true, false><<<dim3(Hn / 128, MT / 128), 256, SM_DD>>>(
        t1h, Hn, wa2, Hn, b_a2, fah, Hn, MT, Hn, Hn, 0, 0, nullptr, nullptr, nullptr);

    // (4,5) G1T [300][512] = hemb^T @ fhR^T : A trans from embh rows LPn.., B = fhR W-form
    hgemm<true, false, 0, false, true><<<dim3(4, 3, NSPL), 256, SM_TD>>>(
        embh + (size_t)LPn * DP, DP, fhR, LHn, nullptr, part, Hn,
        Dn, Hn, LHn, LHn / NSPL, DP, nullptr, nullptr, nullptr);
    reduce_h<<<(Dn * Hn / 4 + TB - 1) / TB, TB>>>(part, G1h, Dn * Hn);

    // (6) E = fp @ fhR, trans-B direct from fhR, fused row/col sums
    hgemm<false, true, 3, false, false><<<dim3(LHn / 128, LPn / 128), 256, SM_DT>>>(
        fah, Hn, fhR, LHn, nullptr, outE, LHn, LPn, LHn, Hn, 0, 0, eik, ekj, nullptr);

    // (7,8) G2T [300][512] = pemb^T @ fp : A trans from embh, B trans from fah
    hgemm<true, true, 0, false, true><<<dim3(4, 3, NSPL), 256, SM_TT>>>(
        embh, DP, fah, Hn, nullptr, part, Hn,
        Dn, Hn, LPn, LPn / NSPL, DP, nullptr, nullptr, nullptr);
    reduce_h<<<(Dn * Hn / 4 + TB - 1) / TB, TB>>>(part, G2h, Dn * Hn);

    // (9) beta = diag(1/eik) * fp @ G1 -> outBeta fp32 + cath halves
    hgemm<false, false, 2, false, false><<<dim3(3, LPn / 128), 256, SM_DD>>>(
        fah, Hn, G1h, Hn, eik, outBeta, Dn, LPn, Dn, Hn, 0, 0, nullptr, nullptr, cath);

    // (10) alpha = diag(1/ekj) * fhR^T @ G2 -> outAlpha fp32 + cath halves
    hgemm<true, false, 2, false, false><<<dim3(3, LHn / 128), 256, SM_TD>>>(
        fhR, LHn, G2h, Hn, ekj, outAlpha, Dn, LHn, Dn, Hn, 0, LHn,
        nullptr, nullptr, cath + (size_t)LPn * CP);

    // (11,12) comp: cath -> t1h -> fused column sums into v
    hgemm<false, false, 1, true, false><<<dim3(Hn / 128, MT / 128), 256, SM_DD>>>(
        cath, CP, wc1, CP, b_c1, t1h, Hn, MT, Hn, CP, 0, 0, nullptr, nullptr, nullptr);
    hgemm<false, false, 4, false, false><<<dim3(Hn / 128, MT / 128), 256, SM_DD>>>(
        t1h, Hn, wc2, Hn, b_c2, nullptr, Hn, MT, Hn, Hn, 0, 0, v, nullptr, nullptr);

    // (13) final head
    final_k<<<1, 1024>>>(W_g1, b_g1, W_g2, b_g2, W_g3, b_g3, outV, outY);
}

// round 13
// speedup vs baseline: 3.7310x; 2.4486x over previous
#include <cuda_runtime.h>
#include <cuda_fp16.h>
#include <cstdint>

#define LPn 4096
#define LHn 4096
#define Dn 300
#define Hn 512
#define NSPL 16
#define DP 304   // Dn padded to x8
#define CP 608   // 2*Dn padded to x8

// ---------------- scratch (device globals; no allocation allowed) ----------
__device__ __half g_embh[(LPn + LHn) * DP];
__device__ __half g_t1h[(LPn + LHn) * Hn];
__device__ __half g_fah[(LPn + LHn) * Hn];
__device__ __half g_cath[(LPn + LHn) * CP];
__device__ __half g_G1h[Dn * Hn];
__device__ __half g_G2h[Dn * Hn];
__device__ __half g_wa1[Hn * DP];
__device__ __half g_wa2[Hn * Hn];
__device__ __half g_wc1[Hn * CP];
__device__ __half g_wc2[Hn * Hn];
__device__ float g_part[NSPL * Dn * Hn];
__device__ float g_eik[LPn];
__device__ float g_ekj[LHn];
__device__ float g_v[2 * Hn];
__device__ float g_y1[Hn];
__device__ float g_y2[Hn];

// ---------------- helpers ---------------------------------------------------
__device__ __forceinline__ void cpa16(uint32_t saddr, const void* g, uint32_t vb) {
    asm volatile("cp.async.cg.shared.global [%0], [%1], 16, %2;"
                 ::"r"(saddr), "l"(g), "r"(vb));
}
#define CP_COMMIT() asm volatile("cp.async.commit_group;" ::: "memory")
#define CP_WAIT1() asm volatile("cp.async.wait_group 1;" ::: "memory")

__device__ __forceinline__ void mma16(float* c, const uint32_t* a, uint32_t b0, uint32_t b1) {
    asm volatile(
        "mma.sync.aligned.m16n8k16.row.col.f32.f16.f16.f32 "
        "{%0,%1,%2,%3}, {%4,%5,%6,%7}, {%8,%9}, {%0,%1,%2,%3};"
        : "+f"(c[0]), "+f"(c[1]), "+f"(c[2]), "+f"(c[3])
        : "r"(a[0]), "r"(a[1]), "r"(a[2]), "r"(a[3]), "r"(b0), "r"(b1));
}
__device__ __forceinline__ void ldm4(uint32_t* r, uint32_t addr) {
    asm volatile("ldmatrix.sync.aligned.m8n8.x4.shared.b16 {%0,%1,%2,%3}, [%4];"
                 : "=r"(r[0]), "=r"(r[1]), "=r"(r[2]), "=r"(r[3]) : "r"(addr));
}
__device__ __forceinline__ void ldm4t(uint32_t* r, uint32_t addr) {
    asm volatile("ldmatrix.sync.aligned.m8n8.x4.trans.shared.b16 {%0,%1,%2,%3}, [%4];"
                 : "=r"(r[0]), "=r"(r[1]), "=r"(r[2]), "=r"(r[3]) : "r"(addr));
}

// direct: src half [rows][ld]; chunk [k0,k0+64) -> smem [r][k] stride 72 halves
__device__ __forceinline__ void loadDirH(const __half* __restrict__ src, int ld,
                                         int row0, int rlim, int k0, int kend,
                                         uint32_t saddr) {
    int t = threadIdx.x;
    int r = t >> 1, kb = (t & 1) * 32;
    int gr = row0 + r;
    bool rok = gr < rlim;
    const __half* p = src + (size_t)(rok ? gr : row0) * ld + k0 + kb;
    uint32_t sa = saddr + (uint32_t)(r * 72 + kb) * 2;
#pragma unroll
    for (int j = 0; j < 4; j++) {
        int gk = k0 + kb + j * 8;
        uint32_t vb = (rok && gk + 8 <= kend) ? 16u : 0u;
        cpa16(sa + j * 16, p + j * 8, vb);
    }
}

// trans: src half [Ktot][ld]; k rows [k0,k0+64), cols [c0,c0+128) -> smem [k][c] stride 136
__device__ __forceinline__ void loadTransH(const __half* __restrict__ src, int ld,
                                           int c0, int clim, int k0, int kend,
                                           uint32_t saddr) {
    int t = threadIdx.x;
    int k = t >> 2;
    int gk = k0 + k;
    bool kok = gk < kend;
    const __half* p = src + (size_t)(kok ? gk : k0) * ld + c0;
    uint32_t sa = saddr + (uint32_t)(k * 136) * 2;
#pragma unroll
    for (int j = 0; j < 4; j++) {
        int moff = ((t & 3) * 4 + j) * 8;
        int gm = c0 + moff;
        uint32_t vb = (kok && gm + 8 <= clim) ? 16u : 0u;
        cpa16(sa + (uint32_t)moff * 2, p + moff, vb);
    }
}

// ---------------- fp16 mma GEMM, cp.async 3-stage, BK=64 -------------------
// AT: A[m,k]=src[k*lda+m] (trans-A). BT: B[k,n]=src[k*ldb+n] (trans-B);
//     else B = W-form [N,K] row-major.
// EPI: 0 plain; 1 bias+relu; 2 rowscale fp32 store + half copy into ph (+Dn);
//      3 store + atomic row sums p1 / col sums p2; 4 bias+relu, atomic col
//      sums into p1 (+Hn for h-rows), no store.
template <bool AT, bool BT, int EPI, bool OH, bool SPLITK>
__global__ void __launch_bounds__(256, 2)
hgemm(const __half* __restrict__ A, int lda,
      const __half* __restrict__ B, int ldb,
      const float* __restrict__ aux,
      void* __restrict__ Cv, int ldc,
      int M, int N, int K, int Ksub, int aclim,
      float* __restrict__ p1, float* __restrict__ p2,
      __half* __restrict__ ph) {
    constexpr int AWH = AT ? 64 * 136 : 128 * 72;
    constexpr int BWH = BT ? 64 * 136 : 128 * 72;
    constexpr int STH = AWH + BWH;
    extern __shared__ __half smh[];
    const uint32_t sbase = (uint32_t)__cvta_generic_to_shared(smh);

    const int tid = threadIdx.x, wid = tid >> 5, lane = tid & 31;
    const int gid = lane >> 2, tig = lane & 3;
    const int wm = wid >> 1, wn = wid & 1;
    const int bm = blockIdx.y * 128, bn = blockIdx.x * 128;

    int k_off = 0, Kloc = K;
    if (SPLITK) {
        k_off = blockIdx.z * Ksub;
        Kloc = Ksub;
        Cv = (void*)((float*)Cv + (size_t)blockIdx.z * M * ldc);
    }
    const int kend = k_off + Kloc;
    const int NC = (Kloc + 63) / 64;

    float acc[2][8][4];
#pragma unroll
    for (int i = 0; i < 2; i++)
#pragma unroll
        for (int j = 0; j < 8; j++)
#pragma unroll
            for (int q = 0; q < 4; q++) acc[i][j][q] = 0.f;

    uint32_t a_off;
    if (AT) {
        int krow = ((lane >> 4) << 3) + (lane & 7);
        int moff = ((lane >> 3) & 1) * 8;
        a_off = (uint32_t)(krow * 136 + wm * 32 + moff) * 2;
    } else {
        a_off = (uint32_t)((wm * 32 + (lane & 15)) * 72 + (lane >> 4) * 8) * 2;
    }
    uint32_t b_off;
    if (BT) {
        int krow = ((lane >> 3) & 1) * 8 + (lane & 7);
        int noff = (lane >> 4) * 8;
        b_off = (uint32_t)AWH * 2 + (uint32_t)(krow * 136 + wn * 64 + noff) * 2;
    } else {
        b_off = (uint32_t)AWH * 2 +
                (uint32_t)((wn * 64 + ((lane >> 4) << 3) + (lane & 7)) * 72 +
                           ((lane >> 3) & 1) * 8) * 2;
    }

#pragma unroll
    for (int pc = 0; pc < 2; pc++) {
        uint32_t sA = sbase + (uint32_t)(pc * STH) * 2;
        uint32_t sB = sA + (uint32_t)AWH * 2;
        int k0 = k_off + pc * 64;
        if (AT) loadTransH(A, lda, bm, aclim, k0, kend, sA);
        else    loadDirH(A, lda, bm, M, k0, kend, sA);
        if (BT) loadTransH(B, ldb, bn, N, k0, kend, sB);
        else    loadDirH(B, ldb, bn, N, k0, kend, sB);
        CP_COMMIT();
    }

    for (int kc = 0; kc < NC; kc++) {
        CP_WAIT1();
        __syncthreads();
        if (kc + 2 < NC) {
            int st = (kc + 2) % 3;
            int k0 = k_off + (kc + 2) * 64;
            uint32_t sA = sbase + (uint32_t)(st * STH) * 2;
            uint32_t sB = sA + (uint32_t)AWH * 2;
            if (AT) loadTransH(A, lda, bm, aclim, k0, kend, sA);
            else    loadDirH(A, lda, bm, M, k0, kend, sA);
            if (BT) loadTransH(B, ldb, bn, N, k0, kend, sB);
            else    loadDirH(B, ldb, bn, N, k0, kend, sB);
        }
        CP_COMMIT();

        const uint32_t stoff = (uint32_t)((kc % 3) * STH) * 2;
#pragma unroll
        for (int kk = 0; kk < 4; kk++) {
            uint32_t a[2][4];
            if (AT) {
                uint32_t ab = sbase + stoff + a_off + (uint32_t)(kk * 16 * 136) * 2;
                ldm4t(a[0], ab);
                ldm4t(a[1], ab + 16 * 2);
            } else {
                uint32_t ab = sbase + stoff + a_off + (uint32_t)(kk * 16) * 2;
                ldm4(a[0], ab);
                ldm4(a[1], ab + (uint32_t)(16 * 72) * 2);
            }
            uint32_t b[8][2];
#pragma unroll
            for (int nj = 0; nj < 4; nj++) {
                uint32_t r[4];
                if (BT) ldm4t(r, sbase + stoff + b_off + (uint32_t)(kk * 16 * 136 + nj * 16) * 2);
                else    ldm4 (r, sbase + stoff + b_off + (uint32_t)(nj * 16 * 72 + kk * 16) * 2);
                b[2 * nj][0] = r[0]; b[2 * nj][1] = r[1];
                b[2 * nj + 1][0] = r[2]; b[2 * nj + 1][1] = r[3];
            }
#pragma unroll
            for (int ni = 0; ni < 8; ni++) {
                mma16(acc[0][ni], a[0], b[ni][0], b[ni][1]);
                mma16(acc[1][ni], a[1], b[ni][0], b[ni][1]);
            }
        }
    }

    // ---------------- epilogue ----------------
    float csum0[8], csum1[8];
    if (EPI == 3 || EPI == 4) {
#pragma unroll
        for (int ni = 0; ni < 8; ni++) { csum0[ni] = 0.f; csum1[ni] = 0.f; }
    }
#pragma unroll
    for (int mi = 0; mi < 2; mi++) {
        int r0 = bm + wm * 32 + mi * 16 + gid;
        float s0 = 1.f, s1 = 1.f;
        if (EPI == 2) {
            if (r0 < M) s0 = 1.f / aux[r0];
            if (r0 + 8 < M) s1 = 1.f / aux[r0 + 8];
        }
        float rs0 = 0.f, rs1 = 0.f;
#pragma unroll
        for (int ni = 0; ni < 8; ni++) {
            int col = bn + wn * 64 + ni * 8 + tig * 2;
            if (col >= N) continue;
            float v0 = acc[mi][ni][0], v1 = acc[mi][ni][1];
            float v2 = acc[mi][ni][2], v3 = acc[mi][ni][3];
            if (EPI == 1 || EPI == 4) {
                float bi0 = aux[col];
                float bi1 = (col + 1 < N) ? aux[col + 1] : 0.f;
                v0 = fmaxf(v0 + bi0, 0.f); v1 = fmaxf(v1 + bi1, 0.f);
                v2 = fmaxf(v2 + bi0, 0.f); v3 = fmaxf(v3 + bi1, 0.f);
            }
            if (EPI == 2) { v0 *= s0; v1 *= s0; v2 *= s1; v3 *= s1; }
            if (EPI != 4) {
                if (OH) {
                    __half* C = (__half*)Cv;
                    if (col + 1 < N) {
                        if (r0 < M) *(__half2*)(C + (size_t)r0 * ldc + col) = __floats2half2_rn(v0, v1);
                        if (r0 + 8 < M) *(__half2*)(C + (size_t)(r0 + 8) * ldc + col) = __floats2half2_rn(v2, v3);
                    } else {
                        if (r0 < M) C[(size_t)r0 * ldc + col] = __float2half_rn(v0);
                        if (r0 + 8 < M) C[(size_t)(r0 + 8) * ldc + col] = __float2half_rn(v2);
                    }
                } else {
                    float* C = (float*)Cv;
                    if (col + 1 < N) {
                        if (r0 < M) *(float2*)(C + (size_t)r0 * ldc + col) = make_float2(v0, v1);
                        if (r0 + 8 < M) *(float2*)(C + (size_t)(r0 + 8) * ldc + col) = make_float2(v2, v3);
                    } else {
                        if (r0 < M) C[(size_t)r0 * ldc + col] = v0;
                        if (r0 + 8 < M) C[(size_t)(r0 + 8) * ldc + col] = v2;
                    }
                }
            }
            if (EPI == 2) {
                if (r0 < M) *(__half2*)(ph + (size_t)r0 * CP + Dn + col) = __floats2half2_rn(v0, v1);
                if (r0 + 8 < M) *(__half2*)(ph + (size_t)(r0 + 8) * CP + Dn + col) = __floats2half2_rn(v2, v3);
            }
            if (EPI == 3) {
                rs0 += v0 + v1; rs1 += v2 + v3;
                csum0[ni] += v0 + v2; csum1[ni] += v1 + v3;
            }
            if (EPI == 4) {
                csum0[ni] += v0 + v2; csum1[ni] += v1 + v3;
            }
        }
        if (EPI == 3) {
            rs0 += __shfl_xor_sync(0xffffffffu, rs0, 1);
            rs0 += __shfl_xor_sync(0xffffffffu, rs0, 2);
            rs1 += __shfl_xor_sync(0xffffffffu, rs1, 1);
            rs1 += __shfl_xor_sync(0xffffffffu, rs1, 2);
            if (tig == 0) {
                atomicAdd(&p1[r0], rs0);
                atomicAdd(&p1[r0 + 8], rs1);
            }
        }
    }
    if (EPI == 3 || EPI == 4) {
        float* cbase = (EPI == 3) ? p2 : (p1 + ((bm >= LPn) ? Hn : 0));
#pragma unroll
        for (int ni = 0; ni < 8; ni++) {
            int col = bn + wn * 64 + ni * 8 + tig * 2;
            if (col >= N) continue;
            float c0 = csum0[ni], c1 = csum1[ni];
            c0 += __shfl_xor_sync(0xffffffffu, c0, 4);
            c0 += __shfl_xor_sync(0xffffffffu, c0, 8);
            c0 += __shfl_xor_sync(0xffffffffu, c0, 16);
            c1 += __shfl_xor_sync(0xffffffffu, c1, 4);
            c1 += __shfl_xor_sync(0xffffffffu, c1, 8);
            c1 += __shfl_xor_sync(0xffffffffu, c1, 16);
            if (gid == 0) {
                atomicAdd(&cbase[col], c0);
                atomicAdd(&cbase[col + 1], c1);
            }
        }
    }
}

// ---------------- merged prep kernel ---------------------------------------
__device__ __forceinline__ void cvt8(const float* p, int sld_valid, __half* dst) {
    __half h[8];
#pragma unroll
    for (int i = 0; i < 8; i++) h[i] = __float2half_rn((i < sld_valid) ? p[i] : 0.f);
    *(uint4*)dst = *(uint4*)h;
}

__global__ void prep_k(const int* __restrict__ p_idx, const int* __restrict__ h_idx,
                       const float* __restrict__ emb,
                       const float* __restrict__ W_a1, const float* __restrict__ W_a2,
                       const float* __restrict__ W_c1, const float* __restrict__ W_c2) {
    int b = blockIdx.x, tid = threadIdx.x;
    if (b < 1216) {  // gather: 8192 rows * 38 groups
        int t = b * 256 + tid;
        int r = t / (DP / 8), g = t - r * (DP / 8);
        int base = g * 8;
        int ix = (r < LPn) ? p_idx[r] : h_idx[r - LPn];
        const float* src = emb + (size_t)ix * Dn;
        __half h[8];
#pragma unroll
        for (int i = 0; i < 8; i++) {
            int c = base + i;
            h[i] = __float2half_rn((c < Dn) ? src[c] : 0.f);
        }
        *(uint4*)(g_embh + (size_t)r * DP + base) = *(uint4*)h;
        *(uint4*)(g_cath + (size_t)r * CP + base) = *(uint4*)h;
        if (g == 0) {
            uint4 z = make_uint4(0u, 0u, 0u, 0u);
            *(uint4*)(g_cath + (size_t)r * CP + 2 * Dn) = z;
        }
    } else if (b < 1292) {  // wa1
        int t = (b - 1216) * 256 + tid;
        int r = t / (DP / 8), g = t - r * (DP / 8);
        int base = g * 8;
        cvt8(W_a1 + (size_t)r * Dn + base, Dn - base, g_wa1 + (size_t)r * DP + base);
    } else if (b < 1420) {  // wa2
        int t = (b - 1292) * 256 + tid;
        int base = (t % (Hn / 8)) * 8, r = t / (Hn / 8);
        cvt8(W_a2 + (size_t)r * Hn + base, 8, g_wa2 + (size_t)r * Hn + base);
    } else if (b < 1572) {  // wc1
        int t = (b - 1420) * 256 + tid;
        int r = t / (CP / 8), g = t - r * (CP / 8);
        int base = g * 8;
        cvt8(W_c1 + (size_t)r * 2 * Dn + base, 2 * Dn - base, g_wc1 + (size_t)r * CP + base);
    } else if (b < 1700) {  // wc2
        int t = (b - 1572) * 256 + tid;
        int base = (t % (Hn / 8)) * 8, r = t / (Hn / 8);
        cvt8(W_c2 + (size_t)r * Hn + base, 8, g_wc2 + (size_t)r * Hn + base);
    } else {  // zero
        int t = (b - 1700) * 256 + tid;
        g_eik[t] = 0.f;
        g_ekj[t] = 0.f;
        if (t < 2 * Hn) g_v[t] = 0.f;
    }
}

__global__ void reduce_h(const float* __restrict__ part, __half* __restrict__ out, int MN) {
    int t = blockIdx.x * blockDim.x + threadIdx.x;
    if (t >= MN / 4) return;
    float4 s = make_float4(0.f, 0.f, 0.f, 0.f);
#pragma unroll
    for (int z = 0; z < NSPL; z++) {
        float4 v = ((const float4*)(part + (size_t)z * MN))[t];
        s.x += v.x; s.y += v.y; s.z += v.z; s.w += v.w;
    }
    ((__half2*)out)[t * 2] = __floats2half2_rn(s.x, s.y);
    ((__half2*)out)[t * 2 + 1] = __floats2half2_rn(s.z, s.w);
}

// ---------------- parallel final head --------------------------------------
// one output neuron per block; block-reduced dot product of length Kd.
__global__ void fin_k(const float* __restrict__ W, const float* __restrict__ b,
                      const float* __restrict__ x, float* __restrict__ y,
                      float* __restrict__ outv, int Kd) {
    int o = blockIdx.x, tid = threadIdx.x, wid = tid >> 5, lane = tid & 31;
    const float4* Wr = (const float4*)(W + (size_t)o * Kd);
    const float4* xr = (const float4*)x;
    float s = 0.f;
    for (int i = tid; i < Kd / 4; i += 256) {
        float4 w = Wr[i], xv = xr[i];
        s += w.x * xv.x + w.y * xv.y + w.z * xv.z + w.w * xv.w;
    }
#pragma unroll
    for (int off = 16; off; off >>= 1) s += __shfl_xor_sync(0xffffffffu, s, off);
    __shared__ float ws[8];
    if (lane == 0) ws[wid] = s;
    __syncthreads();
    if (tid == 0) {
        float t = 0.f;
#pragma unroll
        for (int w = 0; w < 8; w++) t += ws[w];
        y[o] = fmaxf(t + b[o], 0.f);
    }
    if (outv && tid < 2) outv[o * 2 + tid] = x[o * 2 + tid];
}

__global__ void fin3_k(const float* __restrict__ W3, const float* __restrict__ b3,
                       const float* __restrict__ y2, float* __restrict__ outy) {
    __shared__ float z[3];
    int tid = threadIdx.x, c = tid >> 5, lane = tid & 31;
    if (c < 3) {
        float s = 0.f;
        for (int k = lane; k < Hn; k += 32) s += W3[c * Hn + k] * y2[k];
#pragma unroll
        for (int off = 16; off; off >>= 1) s += __shfl_xor_sync(0xffffffffu, s, off);
        if (lane == 0) z[c] = s + b3[c];
    }
    __syncthreads();
    if (tid == 0) {
        float mx = fmaxf(z[0], fmaxf(z[1], z[2]));
        float e0 = expf(z[0] - mx), e1 = expf(z[1] - mx), e2 = expf(z[2] - mx);
        float se = e0 + e1 + e2;
        outy[0] = e0 / se; outy[1] = e1 / se; outy[2] = e2 / se;
    }
}

// ---------------- launch --------------------------------------------------
#define SM_DD (3 * (128 * 72 + 128 * 72) * 2)
#define SM_TD (3 * (64 * 136 + 128 * 72) * 2)
#define SM_DT (3 * (128 * 72 + 64 * 136) * 2)
#define SM_TT (3 * (64 * 136 + 64 * 136) * 2)

extern "C" void kernel_launch(void* const* d_in, const int* in_sizes, int n_in,
                              void* d_out, int out_size) {
    const int*   p_idx = (const int*)d_in[0];
    const int*   h_idx = (const int*)d_in[1];
    const float* emb   = (const float*)d_in[2];
    const float* W_a1  = (const float*)d_in[3];
    const float* b_a1  = (const float*)d_in[4];
    const float* W_a2  = (const float*)d_in[5];
    const float* b_a2  = (const float*)d_in[6];
    const float* W_c1  = (const float*)d_in[7];
    const float* b_c1  = (const float*)d_in[8];
    const float* W_c2  = (const float*)d_in[9];
    const float* b_c2  = (const float*)d_in[10];
    const float* W_g1  = (const float*)d_in[11];
    const float* b_g1  = (const float*)d_in[12];
    const float* W_g2  = (const float*)d_in[13];
    const float* b_g2  = (const float*)d_in[14];
    const float* W_g3  = (const float*)d_in[15];
    const float* b_g3  = (const float*)d_in[16];

    float* out      = (float*)d_out;
    float* outE     = out;
    float* outBeta  = outE + (size_t)LPn * LHn;
    float* outAlpha = outBeta + (size_t)LPn * Dn;
    float* outV     = outAlpha + (size_t)LHn * Dn;
    float* outY     = outV + 2 * Hn;

    __half *embh, *t1h, *fah, *cath, *G1h, *G2h;
    __half *wa1, *wa2, *wc1, *wc2;
    float *part, *eik, *ekj, *v, *y1, *y2;
    cudaGetSymbolAddress((void**)&embh, g_embh);
    cudaGetSymbolAddress((void**)&t1h, g_t1h);
    cudaGetSymbolAddress((void**)&fah, g_fah);
    cudaGetSymbolAddress((void**)&cath, g_cath);
    cudaGetSymbolAddress((void**)&G1h, g_G1h);
    cudaGetSymbolAddress((void**)&G2h, g_G2h);
    cudaGetSymbolAddress((void**)&wa1, g_wa1);
    cudaGetSymbolAddress((void**)&wa2, g_wa2);
    cudaGetSymbolAddress((void**)&wc1, g_wc1);
    cudaGetSymbolAddress((void**)&wc2, g_wc2);
    cudaGetSymbolAddress((void**)&part, g_part);
    cudaGetSymbolAddress((void**)&eik, g_eik);
    cudaGetSymbolAddress((void**)&ekj, g_ekj);
    cudaGetSymbolAddress((void**)&v, g_v);
    cudaGetSymbolAddress((void**)&y1, g_y1);
    cudaGetSymbolAddress((void**)&y2, g_y2);

    cudaFuncSetAttribute(hgemm<false, false, 1, true, false>,  cudaFuncAttributeMaxDynamicSharedMemorySize, SM_DD);
    cudaFuncSetAttribute(hgemm<true, false, 0, false, true>,   cudaFuncAttributeMaxDynamicSharedMemorySize, SM_TD);
    cudaFuncSetAttribute(hgemm<true, true, 0, false, true>,    cudaFuncAttributeMaxDynamicSharedMemorySize, SM_TT);
    cudaFuncSetAttribute(hgemm<false, true, 3, false, false>,  cudaFuncAttributeMaxDynamicSharedMemorySize, SM_DT);
    cudaFuncSetAttribute(hgemm<false, false, 2, false, false>, cudaFuncAttributeMaxDynamicSharedMemorySize, SM_DD);
    cudaFuncSetAttribute(hgemm<true, false, 2, false, false>,  cudaFuncAttributeMaxDynamicSharedMemorySize, SM_TD);
    cudaFuncSetAttribute(hgemm<false, false, 4, false, false>, cudaFuncAttributeMaxDynamicSharedMemorySize, SM_DD);

    const int TB = 256;
    const int MT = LPn + LHn;  // 8192
    const __half* fhR = fah + (size_t)LPn * Hn;  // reshape(fh,[H,LH]) = [512][4096]

    // (1) merged prep
    prep_k<<<1716, TB>>>(p_idx, h_idx, emb, W_a1, W_a2, W_c1, W_c2);

    // (2,3) attend (merged p|h)
    hgemm<false, false, 1, true, false><<<dim3(Hn / 128, MT / 128), 256, SM_DD>>>(
        embh, DP, wa1, DP, b_a1, t1h, Hn, MT, Hn, DP, 0, 0, nullptr, nullptr, nullptr);
    hgemm<false, false, 1, true, false><<<dim3(Hn / 128, MT / 128), 256, SM_DD>>>(
        t1h, Hn, wa2, Hn, b_a2, fah, Hn, MT, Hn, Hn, 0, 0, nullptr, nullptr, nullptr);

    // (4,5) G1T = hemb^T @ fhR^T (split-K 16)
    hgemm<true, false, 0, false, true><<<dim3(4, 3, NSPL), 256, SM_TD>>>(
        embh + (size_t)LPn * DP, DP, fhR, LHn, nullptr, part, Hn,
        Dn, Hn, LHn, LHn / NSPL, DP, nullptr, nullptr, nullptr);
    reduce_h<<<(Dn * Hn / 4 + TB - 1) / TB, TB>>>(part, G1h, Dn * Hn);

    // (6) E = fp @ fhR, trans-B, fused row/col sums
    hgemm<false, true, 3, false, false><<<dim3(LHn / 128, LPn / 128), 256, SM_DT>>>(
        fah, Hn, fhR, LHn, nullptr, outE, LHn, LPn, LHn, Hn, 0, 0, eik, ekj, nullptr);

    // (7,8) G2T = pemb^T @ fp (split-K 16)
    hgemm<true, true, 0, false, true><<<dim3(4, 3, NSPL), 256, SM_TT>>>(
        embh, DP, fah, Hn, nullptr, part, Hn,
        Dn, Hn, LPn, LPn / NSPL, DP, nullptr, nullptr, nullptr);
    reduce_h<<<(Dn * Hn / 4 + TB - 1) / TB, TB>>>(part, G2h, Dn * Hn);

    // (9) beta = diag(1/eik) * fp @ G1 -> outBeta + cath halves
    hgemm<false, false, 2, false, false><<<dim3(3, LPn / 128), 256, SM_DD>>>(
        fah, Hn, G1h, Hn, eik, outBeta, Dn, LPn, Dn, Hn, 0, 0, nullptr, nullptr, cath);

    // (10) alpha = diag(1/ekj) * fhR^T @ G2 -> outAlpha + cath halves
    hgemm<true, false, 2, false, false><<<dim3(3, LHn / 128), 256, SM_TD>>>(
        fhR, LHn, G2h, Hn, ekj, outAlpha, Dn, LHn, Dn, Hn, 0, LHn,
        nullptr, nullptr, cath + (size_t)LPn * CP);

    // (11,12) comp: cath -> t1h -> fused column sums into v
    hgemm<false, false, 1, true, false><<<dim3(Hn / 128, MT / 128), 256, SM_DD>>>(
        cath, CP, wc1, CP, b_c1, t1h, Hn, MT, Hn, CP, 0, 0, nullptr, nullptr, nullptr);
    hgemm<false, false, 4, false, false><<<dim3(Hn / 128, MT / 128), 256, SM_DD>>>(
        t1h, Hn, wc2, Hn, b_c2, nullptr, Hn, MT, Hn, Hn, 0, 0, v, nullptr, nullptr);

    // (13-15) parallel final head
    fin_k<<<Hn, 256>>>(W_g1, b_g1, v, y1, outV, 2 * Hn);
    fin_k<<<Hn, 256>>>(W_g2, b_g2, y1, y2, nullptr, Hn);
    fin3_k<<<1, 128>>>(W_g3, b_g3, y2, outY);
}

// round 14
// speedup vs baseline: 3.7634x; 1.0087x over previous
#include <cuda_runtime.h>
#include <cuda_fp16.h>
#include <cstdint>

#define LPn 4096
#define LHn 4096
#define Dn 300
#define Hn 512
#define NSPL 16
#define DP 304   // Dn padded to x8
#define CP 608   // 2*Dn padded to x8

// ---------------- scratch (device globals; no allocation allowed) ----------
__device__ __half g_embh[(LPn + LHn) * DP];
__device__ __half g_t1h[(LPn + LHn) * Hn];
__device__ __half g_fah[(LPn + LHn) * Hn];
__device__ __half g_cath[(LPn + LHn) * CP];
__device__ __half g_G1h[Dn * Hn];
__device__ __half g_G2h[Dn * Hn];
__device__ __half g_wa1[Hn * DP];
__device__ __half g_wa2[Hn * Hn];
__device__ __half g_wc1[Hn * CP];
__device__ __half g_wc2[Hn * Hn];
__device__ float g_part[NSPL * Dn * Hn];
__device__ float g_part2[NSPL * Dn * Hn];
__device__ float g_eik[LPn];
__device__ float g_ekj[LHn];
__device__ float g_v[2 * Hn];
__device__ float g_y1[Hn];
__device__ float g_y2[Hn];

// ---------------- helpers ---------------------------------------------------
__device__ __forceinline__ void cpa16(uint32_t saddr, const void* g, uint32_t vb) {
    asm volatile("cp.async.cg.shared.global [%0], [%1], 16, %2;"
                 ::"r"(saddr), "l"(g), "r"(vb));
}
#define CP_COMMIT() asm volatile("cp.async.commit_group;" ::: "memory")
#define CP_WAIT1() asm volatile("cp.async.wait_group 1;" ::: "memory")

__device__ __forceinline__ void mma16(float* c, const uint32_t* a, uint32_t b0, uint32_t b1) {
    asm volatile(
        "mma.sync.aligned.m16n8k16.row.col.f32.f16.f16.f32 "
        "{%0,%1,%2,%3}, {%4,%5,%6,%7}, {%8,%9}, {%0,%1,%2,%3};"
        : "+f"(c[0]), "+f"(c[1]), "+f"(c[2]), "+f"(c[3])
        : "r"(a[0]), "r"(a[1]), "r"(a[2]), "r"(a[3]), "r"(b0), "r"(b1));
}
__device__ __forceinline__ void ldm4(uint32_t* r, uint32_t addr) {
    asm volatile("ldmatrix.sync.aligned.m8n8.x4.shared.b16 {%0,%1,%2,%3}, [%4];"
                 : "=r"(r[0]), "=r"(r[1]), "=r"(r[2]), "=r"(r[3]) : "r"(addr));
}
__device__ __forceinline__ void ldm4t(uint32_t* r, uint32_t addr) {
    asm volatile("ldmatrix.sync.aligned.m8n8.x4.trans.shared.b16 {%0,%1,%2,%3}, [%4];"
                 : "=r"(r[0]), "=r"(r[1]), "=r"(r[2]), "=r"(r[3]) : "r"(addr));
}

// direct: src half [rows][ld]; chunk [k0,k0+64) -> smem [r][k] stride 72 halves
__device__ __forceinline__ void loadDirH(const __half* __restrict__ src, int ld,
                                         int row0, int rlim, int k0, int kend,
                                         uint32_t saddr) {
    int t = threadIdx.x;
    int r = t >> 1, kb = (t & 1) * 32;
    int gr = row0 + r;
    bool rok = gr < rlim;
    const __half* p = src + (size_t)(rok ? gr : row0) * ld + k0 + kb;
    uint32_t sa = saddr + (uint32_t)(r * 72 + kb) * 2;
#pragma unroll
    for (int j = 0; j < 4; j++) {
        int gk = k0 + kb + j * 8;
        uint32_t vb = (rok && gk + 8 <= kend) ? 16u : 0u;
        cpa16(sa + j * 16, p + j * 8, vb);
    }
}

// trans: src half [Ktot][ld]; k rows [k0,k0+64), cols [c0,c0+128) -> smem [k][c] stride 136
__device__ __forceinline__ void loadTransH(const __half* __restrict__ src, int ld,
                                           int c0, int clim, int k0, int kend,
                                           uint32_t saddr) {
    int t = threadIdx.x;
    int k = t >> 2;
    int gk = k0 + k;
    bool kok = gk < kend;
    const __half* p = src + (size_t)(kok ? gk : k0) * ld + c0;
    uint32_t sa = saddr + (uint32_t)(k * 136) * 2;
#pragma unroll
    for (int j = 0; j < 4; j++) {
        int moff = ((t & 3) * 4 + j) * 8;
        int gm = c0 + moff;
        uint32_t vb = (kok && gm + 8 <= clim) ? 16u : 0u;
        cpa16(sa + (uint32_t)moff * 2, p + moff, vb);
    }
}

// fragment loaders (per-kk)
template <bool AT>
__device__ __forceinline__ void ldFragA(uint32_t sbase, uint32_t stoff, uint32_t a_off,
                                        int kk, uint32_t a[2][4]) {
    if (AT) {
        uint32_t ab = sbase + stoff + a_off + (uint32_t)(kk * 16 * 136) * 2;
        ldm4t(a[0], ab);
        ldm4t(a[1], ab + 16 * 2);
    } else {
        uint32_t ab = sbase + stoff + a_off + (uint32_t)(kk * 16) * 2;
        ldm4(a[0], ab);
        ldm4(a[1], ab + (uint32_t)(16 * 72) * 2);
    }
}
template <bool BT>
__device__ __forceinline__ void ldFragB(uint32_t sbase, uint32_t stoff, uint32_t b_off,
                                        int kk, uint32_t b[8][2]) {
#pragma unroll
    for (int nj = 0; nj < 4; nj++) {
        uint32_t r[4];
        if (BT) ldm4t(r, sbase + stoff + b_off + (uint32_t)(kk * 16 * 136 + nj * 16) * 2);
        else    ldm4 (r, sbase + stoff + b_off + (uint32_t)(nj * 16 * 72 + kk * 16) * 2);
        b[2 * nj][0] = r[0]; b[2 * nj][1] = r[1];
        b[2 * nj + 1][0] = r[2]; b[2 * nj + 1][1] = r[3];
    }
}

// ---------------- fp16 mma GEMM, cp.async 3-stage, BK=64 -------------------
// AT: A[m,k]=src[k*lda+m]. BT: B[k,n]=src[k*ldb+n]; else B = W-form [N,K].
// EPI: 0 plain; 1 bias+relu; 2 rowscale fp32 store + half copy into ph (+Dn);
//      3 store + atomic row sums p1 / col sums p2; 4 bias+relu, atomic col
//      sums into p1 (+Hn for h-rows), no store.
template <bool AT, bool BT, int EPI, bool OH, bool SPLITK>
__global__ void __launch_bounds__(256, 2)
hgemm(const __half* __restrict__ A, int lda,
      const __half* __restrict__ B, int ldb,
      const float* __restrict__ aux,
      void* __restrict__ Cv, int ldc,
      int M, int N, int K, int Ksub, int aclim,
      float* __restrict__ p1, float* __restrict__ p2,
      __half* __restrict__ ph) {
    constexpr int AWH = AT ? 64 * 136 : 128 * 72;
    constexpr int BWH = BT ? 64 * 136 : 128 * 72;
    constexpr int STH = AWH + BWH;
    extern __shared__ __half smh[];
    const uint32_t sbase = (uint32_t)__cvta_generic_to_shared(smh);

    const int tid = threadIdx.x, wid = tid >> 5, lane = tid & 31;
    const int gid = lane >> 2, tig = lane & 3;
    const int wm = wid >> 1, wn = wid & 1;
    const int bm = blockIdx.y * 128, bn = blockIdx.x * 128;

    int k_off = 0, Kloc = K;
    if (SPLITK) {
        k_off = blockIdx.z * Ksub;
        Kloc = Ksub;
        Cv = (void*)((float*)Cv + (size_t)blockIdx.z * M * ldc);
    }
    const int kend = k_off + Kloc;
    const int NC = (Kloc + 63) / 64;

    float acc[2][8][4];
#pragma unroll
    for (int i = 0; i < 2; i++)
#pragma unroll
        for (int j = 0; j < 8; j++)
#pragma unroll
            for (int q = 0; q < 4; q++) acc[i][j][q] = 0.f;

    uint32_t a_off;
    if (AT) {
        int krow = ((lane >> 4) << 3) + (lane & 7);
        int moff = ((lane >> 3) & 1) * 8;
        a_off = (uint32_t)(krow * 136 + wm * 32 + moff) * 2;
    } else {
        a_off = (uint32_t)((wm * 32 + (lane & 15)) * 72 + (lane >> 4) * 8) * 2;
    }
    uint32_t b_off;
    if (BT) {
        int krow = ((lane >> 3) & 1) * 8 + (lane & 7);
        int noff = (lane >> 4) * 8;
        b_off = (uint32_t)AWH * 2 + (uint32_t)(krow * 136 + wn * 64 + noff) * 2;
    } else {
        b_off = (uint32_t)AWH * 2 +
                (uint32_t)((wn * 64 + ((lane >> 4) << 3) + (lane & 7)) * 72 +
                           ((lane >> 3) & 1) * 8) * 2;
    }

#pragma unroll
    for (int pc = 0; pc < 2; pc++) {
        uint32_t sA = sbase + (uint32_t)(pc * STH) * 2;
        uint32_t sB = sA + (uint32_t)AWH * 2;
        int k0 = k_off + pc * 64;
        if (AT) loadTransH(A, lda, bm, aclim, k0, kend, sA);
        else    loadDirH(A, lda, bm, M, k0, kend, sA);
        if (BT) loadTransH(B, ldb, bn, N, k0, kend, sB);
        else    loadDirH(B, ldb, bn, N, k0, kend, sB);
        CP_COMMIT();
    }

    for (int kc = 0; kc < NC; kc++) {
        CP_WAIT1();
        __syncthreads();
        if (kc + 2 < NC) {
            int st = (kc + 2) % 3;
            int k0 = k_off + (kc + 2) * 64;
            uint32_t sA = sbase + (uint32_t)(st * STH) * 2;
            uint32_t sB = sA + (uint32_t)AWH * 2;
            if (AT) loadTransH(A, lda, bm, aclim, k0, kend, sA);
            else    loadDirH(A, lda, bm, M, k0, kend, sA);
            if (BT) loadTransH(B, ldb, bn, N, k0, kend, sB);
            else    loadDirH(B, ldb, bn, N, k0, kend, sB);
        }
        CP_COMMIT();

        const uint32_t stoff = (uint32_t)((kc % 3) * STH) * 2;
        // fragment double-buffering across kk
        uint32_t a[2][2][4], b[2][8][2];
        ldFragA<AT>(sbase, stoff, a_off, 0, a[0]);
        ldFragB<BT>(sbase, stoff, b_off, 0, b[0]);
#pragma unroll
        for (int kk = 0; kk < 4; kk++) {
            int cur = kk & 1, nxt = cur ^ 1;
            if (kk < 3) {
                ldFragA<AT>(sbase, stoff, a_off, kk + 1, a[nxt]);
                ldFragB<BT>(sbase, stoff, b_off, kk + 1, b[nxt]);
            }
#pragma unroll
            for (int ni = 0; ni < 8; ni++) {
                mma16(acc[0][ni], a[cur][0], b[cur][ni][0], b[cur][ni][1]);
                mma16(acc[1][ni], a[cur][1], b[cur][ni][0], b[cur][ni][1]);
            }
        }
    }

    // ---------------- epilogue ----------------
    float csum0[8], csum1[8];
    if (EPI == 3 || EPI == 4) {
#pragma unroll
        for (int ni = 0; ni < 8; ni++) { csum0[ni] = 0.f; csum1[ni] = 0.f; }
    }
#pragma unroll
    for (int mi = 0; mi < 2; mi++) {
        int r0 = bm + wm * 32 + mi * 16 + gid;
        float s0 = 1.f, s1 = 1.f;
        if (EPI == 2) {
            if (r0 < M) s0 = 1.f / aux[r0];
            if (r0 + 8 < M) s1 = 1.f / aux[r0 + 8];
        }
        float rs0 = 0.f, rs1 = 0.f;
#pragma unroll
        for (int ni = 0; ni < 8; ni++) {
            int col = bn + wn * 64 + ni * 8 + tig * 2;
            if (col >= N) continue;
            float v0 = acc[mi][ni][0], v1 = acc[mi][ni][1];
            float v2 = acc[mi][ni][2], v3 = acc[mi][ni][3];
            if (EPI == 1 || EPI == 4) {
                float bi0 = aux[col];
                float bi1 = (col + 1 < N) ? aux[col + 1] : 0.f;
                v0 = fmaxf(v0 + bi0, 0.f); v1 = fmaxf(v1 + bi1, 0.f);
                v2 = fmaxf(v2 + bi0, 0.f); v3 = fmaxf(v3 + bi1, 0.f);
            }
            if (EPI == 2) { v0 *= s0; v1 *= s0; v2 *= s1; v3 *= s1; }
            if (EPI != 4) {
                if (OH) {
                    __half* C = (__half*)Cv;
                    if (col + 1 < N) {
                        if (r0 < M) *(__half2*)(C + (size_t)r0 * ldc + col) = __floats2half2_rn(v0, v1);
                        if (r0 + 8 < M) *(__half2*)(C + (size_t)(r0 + 8) * ldc + col) = __floats2half2_rn(v2, v3);
                    } else {
                        if (r0 < M) C[(size_t)r0 * ldc + col] = __float2half_rn(v0);
                        if (r0 + 8 < M) C[(size_t)(r0 + 8) * ldc + col] = __float2half_rn(v2);
                    }
                } else {
                    float* C = (float*)Cv;
                    if (col + 1 < N) {
                        if (r0 < M) *(float2*)(C + (size_t)r0 * ldc + col) = make_float2(v0, v1);
                        if (r0 + 8 < M) *(float2*)(C + (size_t)(r0 + 8) * ldc + col) = make_float2(v2, v3);
                    } else {
                        if (r0 < M) C[(size_t)r0 * ldc + col] = v0;
                        if (r0 + 8 < M) C[(size_t)(r0 + 8) * ldc + col] = v2;
                    }
                }
            }
            if (EPI == 2) {
                if (r0 < M) *(__half2*)(ph + (size_t)r0 * CP + Dn + col) = __floats2half2_rn(v0, v1);
                if (r0 + 8 < M) *(__half2*)(ph + (size_t)(r0 + 8) * CP + Dn + col) = __floats2half2_rn(v2, v3);
            }
            if (EPI == 3) {
                rs0 += v0 + v1; rs1 += v2 + v3;
                csum0[ni] += v0 + v2; csum1[ni] += v1 + v3;
            }
            if (EPI == 4) {
                csum0[ni] += v0 + v2; csum1[ni] += v1 + v3;
            }
        }
        if (EPI == 3) {
            rs0 += __shfl_xor_sync(0xffffffffu, rs0, 1);
            rs0 += __shfl_xor_sync(0xffffffffu, rs0, 2);
            rs1 += __shfl_xor_sync(0xffffffffu, rs1, 1);
            rs1 += __shfl_xor_sync(0xffffffffu, rs1, 2);
            if (tig == 0) {
                atomicAdd(&p1[r0], rs0);
                atomicAdd(&p1[r0 + 8], rs1);
            }
        }
    }
    if (EPI == 3 || EPI == 4) {
        float* cbase = (EPI == 3) ? p2 : (p1 + ((bm >= LPn) ? Hn : 0));
#pragma unroll
        for (int ni = 0; ni < 8; ni++) {
            int col = bn + wn * 64 + ni * 8 + tig * 2;
            if (col >= N) continue;
            float c0 = csum0[ni], c1 = csum1[ni];
            c0 += __shfl_xor_sync(0xffffffffu, c0, 4);
            c0 += __shfl_xor_sync(0xffffffffu, c0, 8);
            c0 += __shfl_xor_sync(0xffffffffu, c0, 16);
            c1 += __shfl_xor_sync(0xffffffffu, c1, 4);
            c1 += __shfl_xor_sync(0xffffffffu, c1, 8);
            c1 += __shfl_xor_sync(0xffffffffu, c1, 16);
            if (gid == 0) {
                atomicAdd(&cbase[col], c0);
                atomicAdd(&cbase[col + 1], c1);
            }
        }
    }
}

// ---------------- merged prep kernel ---------------------------------------
__device__ __forceinline__ void cvt8(const float* p, int sld_valid, __half* dst) {
    __half h[8];
#pragma unroll
    for (int i = 0; i < 8; i++) h[i] = __float2half_rn((i < sld_valid) ? p[i] : 0.f);
    *(uint4*)dst = *(uint4*)h;
}

__global__ void prep_k(const int* __restrict__ p_idx, const int* __restrict__ h_idx,
                       const float* __restrict__ emb,
                       const float* __restrict__ W_a1, const float* __restrict__ W_a2,
                       const float* __restrict__ W_c1, const float* __restrict__ W_c2) {
    int b = blockIdx.x, tid = threadIdx.x;
    if (b < 1216) {  // gather: 8192 rows * 38 groups
        int t = b * 256 + tid;
        int r = t / (DP / 8), g = t - r * (DP / 8);
        int base = g * 8;
        int ix = (r < LPn) ? p_idx[r] : h_idx[r - LPn];
        const float* src = emb + (size_t)ix * Dn;
        __half h[8];
#pragma unroll
        for (int i = 0; i < 8; i++) {
            int c = base + i;
            h[i] = __float2half_rn((c < Dn) ? src[c] : 0.f);
        }
        *(uint4*)(g_embh + (size_t)r * DP + base) = *(uint4*)h;
        *(uint4*)(g_cath + (size_t)r * CP + base) = *(uint4*)h;
        if (g == 0) {
            uint4 z = make_uint4(0u, 0u, 0u, 0u);
            *(uint4*)(g_cath + (size_t)r * CP + 2 * Dn) = z;
        }
    } else if (b < 1292) {  // wa1
        int t = (b - 1216) * 256 + tid;
        int r = t / (DP / 8), g = t - r * (DP / 8);
        int base = g * 8;
        cvt8(W_a1 + (size_t)r * Dn + base, Dn - base, g_wa1 + (size_t)r * DP + base);
    } else if (b < 1420) {  // wa2
        int t = (b - 1292) * 256 + tid;
        int base = (t % (Hn / 8)) * 8, r = t / (Hn / 8);
        cvt8(W_a2 + (size_t)r * Hn + base, 8, g_wa2 + (size_t)r * Hn + base);
    } else if (b < 1572) {  // wc1
        int t = (b - 1420) * 256 + tid;
        int r = t / (CP / 8), g = t - r * (CP / 8);
        int base = g * 8;
        cvt8(W_c1 + (size_t)r * 2 * Dn + base, 2 * Dn - base, g_wc1 + (size_t)r * CP + base);
    } else if (b < 1700) {  // wc2
        int t = (b - 1572) * 256 + tid;
        int base = (t % (Hn / 8)) * 8, r = t / (Hn / 8);
        cvt8(W_c2 + (size_t)r * Hn + base, 8, g_wc2 + (size_t)r * Hn + base);
    } else {  // zero
        int t = (b - 1700) * 256 + tid;
        g_eik[t] = 0.f;
        g_ekj[t] = 0.f;
        if (t < 2 * Hn) g_v[t] = 0.f;
    }
}

// merged reduce: section 0 -> G1h from part, section 1 -> G2h from part2
__global__ void reduce2_h(const float* __restrict__ part, const float* __restrict__ part2,
                          __half* __restrict__ o1, __half* __restrict__ o2, int MN) {
    int t = blockIdx.x * blockDim.x + threadIdx.x;
    int half = MN / 4;
    if (t >= 2 * half) return;
    const float* p = (t < half) ? part : part2;
    __half* o = (t < half) ? o1 : o2;
    int ti = (t < half) ? t : t - half;
    float4 s = make_float4(0.f, 0.f, 0.f, 0.f);
#pragma unroll
    for (int z = 0; z < NSPL; z++) {
        float4 v = ((const float4*)(p + (size_t)z * MN))[ti];
        s.x += v.x; s.y += v.y; s.z += v.z; s.w += v.w;
    }
    ((__half2*)o)[ti * 2] = __floats2half2_rn(s.x, s.y);
    ((__half2*)o)[ti * 2 + 1] = __floats2half2_rn(s.z, s.w);
}

// ---------------- parallel final head --------------------------------------
__global__ void fin_k(const float* __restrict__ W, const float* __restrict__ b,
                      const float* __restrict__ x, float* __restrict__ y,
                      float* __restrict__ outv, int Kd) {
    int o = blockIdx.x, tid = threadIdx.x, wid = tid >> 5, lane = tid & 31;
    const float4* Wr = (const float4*)(W + (size_t)o * Kd);
    const float4* xr = (const float4*)x;
    float s = 0.f;
    for (int i = tid; i < Kd / 4; i += 256) {
        float4 w = Wr[i], xv = xr[i];
        s += w.x * xv.x + w.y * xv.y + w.z * xv.z + w.w * xv.w;
    }
#pragma unroll
    for (int off = 16; off; off >>= 1) s += __shfl_xor_sync(0xffffffffu, s, off);
    __shared__ float ws[8];
    if (lane == 0) ws[wid] = s;
    __syncthreads();
    if (tid == 0) {
        float t = 0.f;
#pragma unroll
        for (int w = 0; w < 8; w++) t += ws[w];
        y[o] = fmaxf(t + b[o], 0.f);
    }
    if (outv && tid < 2) outv[o * 2 + tid] = x[o * 2 + tid];
}

__global__ void fin3_k(const float* __restrict__ W3, const float* __restrict__ b3,
                       const float* __restrict__ y2, float* __restrict__ outy) {
    __shared__ float z[3];
    int tid = threadIdx.x, c = tid >> 5, lane = tid & 31;
    if (c < 3) {
        float s = 0.f;
        for (int k = lane; k < Hn; k += 32) s += W3[c * Hn + k] * y2[k];
#pragma unroll
        for (int off = 16; off; off >>= 1) s += __shfl_xor_sync(0xffffffffu, s, off);
        if (lane == 0) z[c] = s + b3[c];
    }
    __syncthreads();
    if (tid == 0) {
        float mx = fmaxf(z[0], fmaxf(z[1], z[2]));
        float e0 = expf(z[0] - mx), e1 = expf(z[1] - mx), e2 = expf(z[2] - mx);
        float se = e0 + e1 + e2;
        outy[0] = e0 / se; outy[1] = e1 / se; outy[2] = e2 / se;
    }
}

// ---------------- launch --------------------------------------------------
#define SM_DD (3 * (128 * 72 + 128 * 72) * 2)
#define SM_TD (3 * (64 * 136 + 128 * 72) * 2)
#define SM_DT (3 * (128 * 72 + 64 * 136) * 2)
#define SM_TT (3 * (64 * 136 + 64 * 136) * 2)

extern "C" void kernel_launch(void* const* d_in, const int* in_sizes, int n_in,
                              void* d_out, int out_size) {
    const int*   p_idx = (const int*)d_in[0];
    const int*   h_idx = (const int*)d_in[1];
    const float* emb   = (const float*)d_in[2];
    const float* W_a1  = (const float*)d_in[3];
    const float* b_a1  = (const float*)d_in[4];
    const float* W_a2  = (const float*)d_in[5];
    const float* b_a2  = (const float*)d_in[6];
    const float* W_c1  = (const float*)d_in[7];
    const float* b_c1  = (const float*)d_in[8];
    const float* W_c2  = (const float*)d_in[9];
    const float* b_c2  = (const float*)d_in[10];
    const float* W_g1  = (const float*)d_in[11];
    const float* b_g1  = (const float*)d_in[12];
    const float* W_g2  = (const float*)d_in[13];
    const float* b_g2  = (const float*)d_in[14];
    const float* W_g3  = (const float*)d_in[15];
    const float* b_g3  = (const float*)d_in[16];

    float* out      = (float*)d_out;
    float* outE     = out;
    float* outBeta  = outE + (size_t)LPn * LHn;
    float* outAlpha = outBeta + (size_t)LPn * Dn;
    float* outV     = outAlpha + (size_t)LHn * Dn;
    float* outY     = outV + 2 * Hn;

    __half *embh, *t1h, *fah, *cath, *G1h, *G2h;
    __half *wa1, *wa2, *wc1, *wc2;
    float *part, *part2, *eik, *ekj, *v, *y1, *y2;
    cudaGetSymbolAddress((void**)&embh, g_embh);
    cudaGetSymbolAddress((void**)&t1h, g_t1h);
    cudaGetSymbolAddress((void**)&fah, g_fah);
    cudaGetSymbolAddress((void**)&cath, g_cath);
    cudaGetSymbolAddress((void**)&G1h, g_G1h);
    cudaGetSymbolAddress((void**)&G2h, g_G2h);
    cudaGetSymbolAddress((void**)&wa1, g_wa1);
    cudaGetSymbolAddress((void**)&wa2, g_wa2);
    cudaGetSymbolAddress((void**)&wc1, g_wc1);
    cudaGetSymbolAddress((void**)&wc2, g_wc2);
    cudaGetSymbolAddress((void**)&part, g_part);
    cudaGetSymbolAddress((void**)&part2, g_part2);
    cudaGetSymbolAddress((void**)&eik, g_eik);
    cudaGetSymbolAddress((void**)&ekj, g_ekj);
    cudaGetSymbolAddress((void**)&v, g_v);
    cudaGetSymbolAddress((void**)&y1, g_y1);
    cudaGetSymbolAddress((void**)&y2, g_y2);

    cudaFuncSetAttribute(hgemm<false, false, 1, true, false>,  cudaFuncAttributeMaxDynamicSharedMemorySize, SM_DD);
    cudaFuncSetAttribute(hgemm<true, false, 0, false, true>,   cudaFuncAttributeMaxDynamicSharedMemorySize, SM_TD);
    cudaFuncSetAttribute(hgemm<true, true, 0, false, true>,    cudaFuncAttributeMaxDynamicSharedMemorySize, SM_TT);
    cudaFuncSetAttribute(hgemm<false, true, 3, false, false>,  cudaFuncAttributeMaxDynamicSharedMemorySize, SM_DT);
    cudaFuncSetAttribute(hgemm<false, false, 2, false, false>, cudaFuncAttributeMaxDynamicSharedMemorySize, SM_DD);
    cudaFuncSetAttribute(hgemm<true, false, 2, false, false>,  cudaFuncAttributeMaxDynamicSharedMemorySize, SM_TD);
    cudaFuncSetAttribute(hgemm<false, false, 4, false, false>, cudaFuncAttributeMaxDynamicSharedMemorySize, SM_DD);

    const int TB = 256;
    const int MT = LPn + LHn;  // 8192
    const __half* fhR = fah + (size_t)LPn * Hn;  // reshape(fh,[H,LH]) = [512][4096]

    // (1) merged prep
    prep_k<<<1716, TB>>>(p_idx, h_idx, emb, W_a1, W_a2, W_c1, W_c2);

    // (2,3) attend (merged p|h)
    hgemm<false, false, 1, true, false><<<dim3(Hn / 128, MT / 128), 256, SM_DD>>>(
        embh, DP, wa1, DP, b_a1, t1h, Hn, MT, Hn, DP, 0, 0, nullptr, nullptr, nullptr);
    hgemm<false, false, 1, true, false><<<dim3(Hn / 128, MT / 128), 256, SM_DD>>>(
        t1h, Hn, wa2, Hn, b_a2, fah, Hn, MT, Hn, Hn, 0, 0, nullptr, nullptr, nullptr);

    // (4,5) G1T = hemb^T @ fhR^T ; G2T = pemb^T @ fp (split-K 16, separate partials)
    hgemm<true, false, 0, false, true><<<dim3(4, 3, NSPL), 256, SM_TD>>>(
        embh + (size_t)LPn * DP, DP, fhR, LHn, nullptr, part, Hn,
        Dn, Hn, LHn, LHn / NSPL, DP, nullptr, nullptr, nullptr);
    hgemm<true, true, 0, false, true><<<dim3(4, 3, NSPL), 256, SM_TT>>>(
        embh, DP, fah, Hn, nullptr, part2, Hn,
        Dn, Hn, LPn, LPn / NSPL, DP, nullptr, nullptr, nullptr);

    // (6) merged reduce -> G1h, G2h
    reduce2_h<<<(2 * Dn * Hn / 4 + TB - 1) / TB, TB>>>(part, part2, G1h, G2h, Dn * Hn);

    // (7) E = fp @ fhR, trans-B, fused row/col sums
    hgemm<false, true, 3, false, false><<<dim3(LHn / 128, LPn / 128), 256, SM_DT>>>(
        fah, Hn, fhR, LHn, nullptr, outE, LHn, LPn, LHn, Hn, 0, 0, eik, ekj, nullptr);

    // (8) beta = diag(1/eik) * fp @ G1 -> outBeta + cath halves
    hgemm<false, false, 2, false, false><<<dim3(3, LPn / 128), 256, SM_DD>>>(
        fah, Hn, G1h, Hn, eik, outBeta, Dn, LPn, Dn, Hn, 0, 0, nullptr, nullptr, cath);

    // (9) alpha = diag(1/ekj) * fhR^T @ G2 -> outAlpha + cath halves
    hgemm<true, false, 2, false, false><<<dim3(3, LHn / 128), 256, SM_TD>>>(
        fhR, LHn, G2h, Hn, ekj, outAlpha, Dn, LHn, Dn, Hn, 0, LHn,
        nullptr, nullptr, cath + (size_t)LPn * CP);

    // (10,11) comp: cath -> t1h -> fused column sums into v
    hgemm<false, false, 1, true, false><<<dim3(Hn / 128, MT / 128), 256, SM_DD>>>(
        cath, CP, wc1, CP, b_c1, t1h, Hn, MT, Hn, CP, 0, 0, nullptr, nullptr, nullptr);
    hgemm<false, false, 4, false, false><<<dim3(Hn / 128, MT / 128), 256, SM_DD>>>(
        t1h, Hn, wc2, Hn, b_c2, nullptr, Hn, MT, Hn, Hn, 0, 0, v, nullptr, nullptr);

    // (12-14) parallel final head
    fin_k<<<Hn, 256>>>(W_g1, b_g1, v, y1, outV, 2 * Hn);
    fin_k<<<Hn, 256>>>(W_g2, b_g2, y1, y2, nullptr, Hn);
    fin3_k<<<1, 128>>>(W_g3, b_g3, y2, outY);
}